// round 12
// baseline (speedup 1.0000x reference)
#include <cuda_runtime.h>
#include <cuda_fp16.h>
#include <cooperative_groups.h>
#include <math.h>

namespace cg = cooperative_groups;

// ============================================================================
// DGISubgraphCL — 4-launch pipeline:
//   csr (dual CSR + fp16 feat + permuted neg feat) ->
//   bfs_dual (frontier BFS + top-k for both perms, fused annotate tail) ->
//   mega GCN (4 streams, fp16 aggregation, f32x2 GEMV 2 nodes/warp, static
//   smem; last block computes v) -> loss (fp16 h; last block finalizes).
// ============================================================================

#define N_MAX 131072
#define E_MAX (N_MAX * 17)
#define HIST_BINS 15001
#define CSRB 264
#define BFSB 132
#define GB 66
#define MAX_SWEEPS 250

typedef unsigned long long ull;

// ---- device scratch ----
__device__ int g_rowD[N_MAX + 1], g_cntD[N_MAX], g_curD[N_MAX];
__device__ int g_rowS[N_MAX + 1], g_cntS[N_MAX], g_curS[N_MAX];
__device__ unsigned g_colD[E_MAX];          // after annotate: s | k1<<30 | k2<<31
__device__ int g_colS[E_MAX];
__device__ __half g_feat16[(size_t)N_MAX * 64];
__device__ __half g_featneg16[(size_t)N_MAX * 64];
__device__ float g_inv1[N_MAX], g_inv2[N_MAX], g_invd[N_MAX];
__device__ int g_hopG[2][N_MAX];
__device__ int g_front[2][2][N_MAX];
__device__ int g_invpermG[2][N_MAX];
__device__ int g_histG[2][HIST_BINS];
__device__ int g_szHist[2][MAX_SWEEPS + 8];
__device__ unsigned char g_keep1[N_MAX];
__device__ unsigned char g_keep2[N_MAX];
__device__ __half g_hpos16[(size_t)N_MAX * 64];
__device__ __half g_hneg16[(size_t)N_MAX * 64];
__device__ double g_summary[128];
__device__ float g_v[2][64];
__device__ double g_loss[4];

__device__ int g_bsD[CSRB], g_bsS[CSRB], g_offD[CSRB], g_offS[CSRB];
__device__ int g_blkCntG[2][GB];
__device__ unsigned long long g_seedkeyG[2];
__device__ int g_hstarG[2], g_rremG[2], g_pstarG[2], g_pselBlockG[2], g_pselRemG[2];

__device__ unsigned g_barC = 0;
__device__ unsigned g_barG[2] = {0, 0};
__device__ unsigned g_barAll = 0, g_barAll2 = 0;
__device__ unsigned g_ctrMega = 0;
__device__ unsigned g_ctrLoss = 0;

// ============================================================================
// helpers
// ============================================================================

__device__ __forceinline__ ull pack2(float x, float y) {
    ull r; asm("mov.b64 %0, {%1, %2};" : "=l"(r) : "f"(x), "f"(y)); return r;
}
__device__ __forceinline__ void unpack2(ull v, float& x, float& y) {
    asm("mov.b64 {%0, %1}, %2;" : "=f"(x), "=f"(y) : "l"(v));
}
__device__ __forceinline__ ull fma2(ull a, ull b, ull c) {
    ull d; asm("fma.rn.f32x2 %0, %1, %2, %3;" : "=l"(d) : "l"(a), "l"(b), "l"(c)); return d;
}
__device__ __forceinline__ __half2 u2h2(unsigned u) {
    __half2 h; *reinterpret_cast<unsigned*>(&h) = u; return h;
}

__device__ __forceinline__ void xsync(unsigned* ctr, unsigned nblk, unsigned& epoch) {
    __syncthreads();
    if (threadIdx.x == 0) {
        __threadfence();
        unsigned target = (epoch + 1) * nblk;
        atomicAdd(ctr, 1u);
        while (*((volatile unsigned*)ctr) < target) {}
        __threadfence();
    }
    epoch++;
    __syncthreads();
}

__device__ __forceinline__ void xexit(unsigned* ctr, unsigned nblk, unsigned epoch) {
    __syncthreads();
    if (threadIdx.x == 0) {
        __threadfence();
        unsigned target = (epoch + 1) * nblk;
        if (atomicAdd(ctr, 1u) + 1 == target) *ctr = 0;
    }
}

__device__ __forceinline__ float softplusf(float x) {
    return fmaxf(x, 0.f) + log1pf(expf(-fabsf(x)));
}

__device__ __forceinline__ unsigned long long ullmin2(unsigned long long a, unsigned long long b) {
    return a < b ? a : b;
}

__device__ __forceinline__ int blockScanInc(int v, int* sWarp) {
    int lane = threadIdx.x & 31;
    int wid = threadIdx.x >> 5;
#pragma unroll
    for (int off = 1; off < 32; off <<= 1) {
        int t = __shfl_up_sync(0xffffffffu, v, off);
        if (lane >= off) v += t;
    }
    if (lane == 31) sWarp[wid] = v;
    __syncthreads();
    if (wid == 0) {
        int w = sWarp[lane];
#pragma unroll
        for (int off = 1; off < 32; off <<= 1) {
            int t = __shfl_up_sync(0xffffffffu, w, off);
            if (lane >= off) w += t;
        }
        sWarp[lane] = w;
    }
    __syncthreads();
    return v + (wid ? sWarp[wid - 1] : 0);
}

// ============================================================================
// Kernel 1: dual CSR build + feat->fp16 (+ permuted neg table) + zeroing
// ============================================================================

__global__ __launch_bounds__(1024, 2)
void csr_kernel(const float* __restrict__ feat, const int* __restrict__ src,
                const int* __restrict__ dst, const int* __restrict__ permneg,
                int e, int n) {
    unsigned epoch = 0;
    int gtid = blockIdx.x * 1024 + threadIdx.x;
    int gsz = gridDim.x * 1024;

    for (int i = gtid; i < n; i += gsz) { g_cntD[i] = 0; g_cntS[i] = 0; }
    if (gtid < 4) g_loss[gtid] = 0.0;
    if (gtid < 128) g_summary[gtid] = 0.0;
    if (gtid == 0) { g_rowD[n] = e; g_rowS[n] = e; }
    {
        int tot = n * 32;
        const float2* f2 = reinterpret_cast<const float2*>(feat);
        __half2* h2 = reinterpret_cast<__half2*>(g_feat16);
        for (int i = gtid; i < tot; i += gsz) h2[i] = __float22half2_rn(f2[i]);
    }
    xsync(&g_barC, gridDim.x, epoch);

    for (int i = gtid; i < e; i += gsz) {
        atomicAdd(&g_cntD[dst[i]], 1);
        atomicAdd(&g_cntS[src[i]], 1);
    }
    {
        int warp = gtid >> 5, lane = gtid & 31, nw = gsz >> 5;
        const __half2* fsrc = reinterpret_cast<const __half2*>(g_feat16);
        __half2* fdst = reinterpret_cast<__half2*>(g_featneg16);
        for (int i = warp; i < n; i += nw) {
            int r = __ldg(&permneg[i]);
            fdst[(size_t)i * 32 + lane] = fsrc[(size_t)r * 32 + lane];
        }
    }
    xsync(&g_barC, gridDim.x, epoch);

    __shared__ int sWarp[32];
    __shared__ int sRun, sTot;
    int chunk = (n + gridDim.x - 1) / gridDim.x;
    int b0 = blockIdx.x * chunk;
    int b1 = min(b0 + chunk, n);
    for (int which = 0; which < 2; which++) {
        int* cnt = which ? g_cntS : g_cntD;
        int* row = which ? g_rowS : g_rowD;
        int* bs = which ? g_bsS : g_bsD;
        if (threadIdx.x == 0) sRun = 0;
        __syncthreads();
        for (int base = b0; base < b1; base += 1024) {
            int i = base + threadIdx.x;
            int v = (i < b1) ? __ldcg(&cnt[i]) : 0;
            int incl = blockScanInc(v, sWarp);
            if (i < b1) row[i] = sRun + incl - v;
            if (threadIdx.x == 1023) sTot = incl;
            __syncthreads();
            if (threadIdx.x == 0) sRun += sTot;
            __syncthreads();
        }
        if (threadIdx.x == 0) bs[blockIdx.x] = sRun;
        __syncthreads();
    }
    xsync(&g_barC, gridDim.x, epoch);

    if (blockIdx.x == 0) {
        int b = threadIdx.x;
        int vD = (b < (int)gridDim.x) ? __ldcg(&g_bsD[b]) : 0;
        int incl = blockScanInc(vD, sWarp);
        if (b < (int)gridDim.x) g_offD[b] = incl - vD;
        int vS = (b < (int)gridDim.x) ? __ldcg(&g_bsS[b]) : 0;
        incl = blockScanInc(vS, sWarp);
        if (b < (int)gridDim.x) g_offS[b] = incl - vS;
    }
    xsync(&g_barC, gridDim.x, epoch);

    {
        int oD = __ldcg(&g_offD[blockIdx.x]);
        int oS = __ldcg(&g_offS[blockIdx.x]);
        for (int i = b0 + threadIdx.x; i < b1; i += 1024) {
            int vD = __ldcg(&g_rowD[i]) + oD;
            int vS = __ldcg(&g_rowS[i]) + oS;
            g_rowD[i] = vD; g_curD[i] = vD;
            g_rowS[i] = vS; g_curS[i] = vS;
        }
    }
    xsync(&g_barC, gridDim.x, epoch);

    for (int i = gtid; i < e; i += gsz) {
        int d = dst[i], s = src[i];
        int pd = atomicAdd(&g_curD[d], 1);
        g_colD[pd] = (unsigned)s;
        int ps = atomicAdd(&g_curS[s], 1);
        g_colS[ps] = d;
    }
    xexit(&g_barC, gridDim.x, epoch);
}

// ============================================================================
// Kernel 2: dual frontier-BFS + exact top-k + FUSED annotate tail
// ============================================================================

__global__ __launch_bounds__(1024, 1)
void bfs_dual_kernel(const int* __restrict__ perm1, const int* __restrict__ perm2, int n, int k) {
    int g = (blockIdx.x < GB) ? 0 : 1;
    int gb = blockIdx.x - g * GB;
    const int* perm = g ? perm2 : perm1;
    unsigned char* keep = g ? g_keep2 : g_keep1;
    int* hop = g_hopG[g];
    int* invp = g_invpermG[g];
    int* hist = g_histG[g];
    unsigned* bar = &g_barG[g];
    unsigned epoch = 0;
    int gtid = gb * 1024 + threadIdx.x;
    int gsz = GB * 1024;
    const int INF = n;

    __shared__ int sWarp[32];
    __shared__ unsigned long long sK[32];

    int root = __ldg(&perm[0]);
    for (int i = gtid; i < n; i += gsz) {
        __stcg(&hop[i], (i == root) ? 0 : INF);
        __stcg(&invp[__ldg(&perm[i])], i);
    }
    for (int i = gtid; i < HIST_BINS; i += gsz) __stcg(&hist[i], 0);
    for (int i = gtid; i < MAX_SWEEPS + 8; i += gsz) __stcg(&g_szHist[g][i], 0);
    if (gtid == 0) {
        __stcg(&g_front[g][0][0], root);
        __stcg(&g_szHist[g][0], 1);
        g_seedkeyG[g] = ~0ull;
    }
    xsync(bar, GB, epoch);

    int cnt = 1;
    int t = 0;
    int lane = threadIdx.x & 31;
    while (cnt <= k && t < MAX_SWEEPS) {
        int fsz = __ldcg(&g_szHist[g][t]);
        const int* fin = g_front[g][t & 1];
        int* fout = g_front[g][(t + 1) & 1];
        int* ctr = &g_szHist[g][t + 1];
        for (int idx = gtid; idx < fsz; idx += gsz) {
            int u = __ldcg(&fin[idx]);
            int s0 = g_rowS[u], s1 = g_rowS[u + 1];
            for (int e2 = s0; e2 < s1; e2++) {
                int v = g_colS[e2];
                bool win = false;
                if (__ldcg(&hop[v]) == INF)
                    win = (atomicCAS(&hop[v], INF, t + 1) == INF);
                if (win) {
                    cg::coalesced_group grp = cg::coalesced_threads();
                    int base;
                    if (grp.thread_rank() == 0) base = atomicAdd(ctr, (int)grp.size());
                    base = grp.shfl(base, 0);
                    __stcg(&fout[base + grp.thread_rank()], v);
                }
            }
        }
        xsync(bar, GB, epoch);
        int newly = __ldcg(&g_szHist[g][t + 1]);
        t += 1;
        cnt += newly;
        if (newly == 0 && cnt <= k) {
            unsigned long long key = ~0ull;
            for (int i = gtid; i < n; i += gsz) {
                if (__ldcg(&hop[i]) == INF)
                    key = ullmin2(key, ((unsigned long long)(unsigned)__ldg(&perm[i]) << 32) | (unsigned)i);
            }
#pragma unroll
            for (int off = 16; off; off >>= 1)
                key = ullmin2(key, __shfl_down_sync(0xffffffffu, key, off));
            int wid = threadIdx.x >> 5;
            if (lane == 0) sK[wid] = key;
            __syncthreads();
            if (threadIdx.x < 32) {
                unsigned long long kk2 = sK[threadIdx.x];
#pragma unroll
                for (int off = 16; off; off >>= 1)
                    kk2 = ullmin2(kk2, __shfl_down_sync(0xffffffffu, kk2, off));
                if (threadIdx.x == 0 && kk2 != ~0ull) atomicMin(&g_seedkeyG[g], kk2);
            }
            xsync(bar, GB, epoch);
            if (gtid == 0) {
                unsigned long long kv = g_seedkeyG[g];
                int idx = (int)(unsigned)(kv & 0xffffffffull);
                __stcg(&hop[idx], t);
                __stcg(&g_front[g][t & 1][0], idx);
                __stcg(&g_szHist[g][t], 1);
                g_seedkeyG[g] = ~0ull;
            }
            cnt += 1;
            xsync(bar, GB, epoch);
        }
    }

    {
        __shared__ int sh[256];
        for (int j = threadIdx.x; j < 256; j += 1024) sh[j] = 0;
        __syncthreads();
        for (int i = gtid; i < n; i += gsz) {
            int hv = min(__ldcg(&hop[i]), 15000);
            if (hv < 256) atomicAdd(&sh[hv], 1);
            else atomicAdd(&hist[hv], 1);
        }
        __syncthreads();
        for (int j = threadIdx.x; j < 256; j += 1024)
            if (sh[j]) atomicAdd(&hist[j], sh[j]);
    }
    xsync(bar, GB, epoch);

    if (gb == 0) {
        __shared__ int sRun, sTot, sDone;
        if (threadIdx.x == 0) { sRun = 0; sDone = 0; }
        __syncthreads();
        for (int base = 0; base < HIST_BINS; base += 1024) {
            if (sDone) break;
            int h = base + threadIdx.x;
            int v = (h < HIST_BINS) ? __ldcg(&hist[h]) : 0;
            int incl = blockScanInc(v, sWarp);
            int P = sRun + incl;
            if (v > 0 && P >= k && P - v < k) { g_hstarG[g] = h; g_rremG[g] = k - (P - v); sDone = 1; }
            if (threadIdx.x == 1023) sTot = incl;
            __syncthreads();
            if (threadIdx.x == 0) sRun += sTot;
            __syncthreads();
        }
    }
    xsync(bar, GB, epoch);
    int hstar = *(volatile int*)&g_hstarG[g];
    int rrem = *(volatile int*)&g_rremG[g];

    int chunk = (n + GB - 1) / GB;
    int v0 = gb * chunk, v1 = min(v0 + chunk, n);
    {
        int c = 0;
        for (int v = v0 + threadIdx.x; v < v1; v += 1024) {
            int j = __ldcg(&invp[v]);
            c += (min(__ldcg(&hop[j]), 15000) == hstar);
        }
#pragma unroll
        for (int off = 16; off; off >>= 1) c += __shfl_down_sync(0xffffffffu, c, off);
        int wid = threadIdx.x >> 5;
        if (lane == 0) sWarp[wid] = c;
        __syncthreads();
        if (threadIdx.x < 32) {
            int r = sWarp[threadIdx.x];
#pragma unroll
            for (int off = 16; off; off >>= 1) r += __shfl_down_sync(0xffffffffu, r, off);
            if (threadIdx.x == 0) g_blkCntG[g][gb] = r;
        }
    }
    xsync(bar, GB, epoch);
    if (gb == 0) {
        int b = threadIdx.x;
        int v = (b < GB) ? __ldcg(&g_blkCntG[g][b]) : 0;
        int incl = blockScanInc(v, sWarp);
        int excl = incl - v;
        if (b < GB && v > 0 && excl < rrem && rrem <= incl) {
            g_pselBlockG[g] = b; g_pselRemG[g] = rrem - excl;
        }
    }
    xsync(bar, GB, epoch);
    if (gb == *(volatile int*)&g_pselBlockG[g]) {
        int rem = *(volatile int*)&g_pselRemG[g];
        __shared__ int sRun2, sTot2, sDone2;
        if (threadIdx.x == 0) { sRun2 = 0; sDone2 = 0; }
        __syncthreads();
        for (int base = v0; base < v1; base += 1024) {
            if (sDone2) break;
            int v = base + threadIdx.x;
            int pred = 0;
            if (v < v1) {
                int j = __ldcg(&invp[v]);
                pred = (min(__ldcg(&hop[j]), 15000) == hstar);
            }
            int incl = blockScanInc(pred, sWarp);
            int cum = sRun2 + incl;
            if (pred && cum == rem) { g_pstarG[g] = v; sDone2 = 1; }
            if (threadIdx.x == 1023) sTot2 = incl;
            __syncthreads();
            if (threadIdx.x == 0) sRun2 += sTot2;
            __syncthreads();
        }
    }
    xsync(bar, GB, epoch);
    int pstar = *(volatile int*)&g_pstarG[g];
    for (int i = gtid; i < n; i += gsz) {
        int hv = min(__ldcg(&hop[i]), 15000);
        keep[i] = (hv < hstar) || (hv == hstar && __ldg(&perm[i]) <= pstar);
    }

    // ---- join both groups, then fused annotate (keep bits + inverse degs) ----
    __syncthreads();
    if (threadIdx.x == 0) {
        __threadfence();
        atomicAdd(&g_barAll, 1u);
        while (*((volatile unsigned*)&g_barAll) < (unsigned)gridDim.x) {}
        __threadfence();
    }
    __syncthreads();

    {
        int warpId = blockIdx.x * 32 + (threadIdx.x >> 5);
        int nW = gridDim.x * 32;
        for (int node = warpId; node < n; node += nW) {
            int s0 = g_rowD[node], s1 = g_rowD[node + 1];
            int c1 = 0, c2 = 0;
            for (int e = s0 + lane; e < s1; e += 32) {
                unsigned c = __ldcg(&g_colD[e]) & 0x3FFFFFFFu;
                unsigned k1 = (unsigned)__ldcg(&g_keep1[c]);
                unsigned k2 = (unsigned)__ldcg(&g_keep2[c]);
                __stcg(&g_colD[e], c | (k1 << 30) | (k2 << 31));
                c1 += (int)k1; c2 += (int)k2;
            }
#pragma unroll
            for (int off = 16; off; off >>= 1) {
                c1 += __shfl_down_sync(0xffffffffu, c1, off);
                c2 += __shfl_down_sync(0xffffffffu, c2, off);
            }
            if (lane == 0) {
                g_inv1[node] = 1.f / (float)max(c1, 1);
                g_inv2[node] = 1.f / (float)max(c2, 1);
                g_invd[node] = 1.f / (float)max(s1 - s0, 1);
            }
        }
    }

    // reset barriers (each block arrives once; last arriver resets both)
    __syncthreads();
    if (threadIdx.x == 0) {
        __threadfence();
        if (atomicAdd(&g_barAll2, 1u) + 1 == (unsigned)gridDim.x) {
            g_barAll = 0; g_barAll2 = 0;
        }
    }
    xexit(bar, GB, epoch);
}

// ============================================================================
// Kernel 3: mega GCN — fp16 aggregation of 4 streams, f32x2 GEMV 2 nodes/warp,
// static smem, fp16 h output; LAST block computes v.
// ============================================================================

#define MEGA_EDGE(cc)                                                          \
    do {                                                                       \
        unsigned s_ = (cc) & 0x3FFFFFFFu;                                      \
        __half2 f_ = FP[(size_t)s_ * 32 + lane];                               \
        __half2 g_ = FN[(size_t)s_ * 32 + lane];                               \
        aP = __hadd2(aP, f_);                                                  \
        aN = __hadd2(aN, g_);                                                  \
        unsigned b1_ = (unsigned)(((int)((cc) << 1)) >> 31) & 0x3C003C00u;     \
        unsigned b2_ = (unsigned)(((int)(cc)) >> 31) & 0x3C003C00u;            \
        aM1 = __hfma2(f_, u2h2(b1_), aM1);                                     \
        aM2 = __hfma2(f_, u2h2(b2_), aM2);                                     \
    } while (0)

__global__ __launch_bounds__(256)
void mega_gcn_kernel(const float* __restrict__ Wenc, const float* __restrict__ Wdisc,
                     int n, int k) {
    __shared__ float sW[4096];
    __shared__ __align__(8) float sxp[8][64][2];
    __shared__ __align__(8) float sxn[8][64][2];
    __shared__ __align__(8) float sx1[8][64][2];
    __shared__ __align__(8) float sx2[8][64][2];
    __shared__ double sSum[128];
    __shared__ int sLast;
    int tid = threadIdx.x;
    for (int j = tid; j < 4096; j += 256) sW[j] = Wenc[j];
    if (tid < 128) sSum[tid] = 0.0;
    __syncthreads();
    int warp = tid >> 5, lane = tid & 31;
    double A10 = 0.0, A11 = 0.0, A20 = 0.0, A21 = 0.0;
    const __half2* FP = reinterpret_cast<const __half2*>(g_feat16);
    const __half2* FN = reinterpret_cast<const __half2*>(g_featneg16);

    for (int nb = (blockIdx.x * 8 + warp) * 2; nb < n; nb += gridDim.x * 16) {
        int k1d[2], k2d[2];
#pragma unroll
        for (int j = 0; j < 2; j++) {
            int node = nb + j;
            bool valid = node < n;
            k1d[j] = valid ? (int)g_keep1[node] : 0;
            k2d[j] = valid ? (int)g_keep2[node] : 0;
            int s0 = valid ? g_rowD[node] : 0;
            int s1 = valid ? g_rowD[node + 1] : 0;

            __half2 aP = u2h2(0), aN = u2h2(0), aM1 = u2h2(0), aM2 = u2h2(0);

            int e2 = s0;
            while (e2 < s1 && (e2 & 3)) { MEGA_EDGE(__ldcs(&g_colD[e2])); e2++; }
            for (; e2 + 4 <= s1; e2 += 4) {
                uint4 c4 = *reinterpret_cast<const uint4*>(&g_colD[e2]);
                MEGA_EDGE(c4.x); MEGA_EDGE(c4.y); MEGA_EDGE(c4.z); MEGA_EDGE(c4.w);
            }
            while (e2 < s1) { MEGA_EDGE(__ldcs(&g_colD[e2])); e2++; }

            float invd = valid ? __ldg(&g_invd[node]) : 1.f;
            float i1 = valid ? __ldg(&g_inv1[node]) : 1.f;
            float i2 = valid ? __ldg(&g_inv2[node]) : 1.f;
            float2 P = __half22float2(aP), Q = __half22float2(aN);
            float2 M1 = __half22float2(aM1), M2 = __half22float2(aM2);
            sxp[warp][2 * lane][j] = P.x * invd; sxp[warp][2 * lane + 1][j] = P.y * invd;
            sxn[warp][2 * lane][j] = Q.x * invd; sxn[warp][2 * lane + 1][j] = Q.y * invd;
            sx1[warp][2 * lane][j] = M1.x * i1;  sx1[warp][2 * lane + 1][j] = M1.y * i1;
            sx2[warp][2 * lane][j] = M2.x * i2;  sx2[warp][2 * lane + 1][j] = M2.y * i2;
        }
        __syncwarp();

        // f32x2 packed GEMV: each ull accumulator = (node0, node1)
        ull oPa = 0, oPb = 0, oNa = 0, oNb = 0;
        ull o1a = 0, o1b = 0, o2a = 0, o2b = 0;
#pragma unroll 16
        for (int kk = 0; kk < 64; kk++) {
            float2 w = *reinterpret_cast<const float2*>(&sW[kk * 64 + 2 * lane]);
            ull wa = pack2(w.x, w.x);
            ull wb = pack2(w.y, w.y);
            ull xp = *reinterpret_cast<const ull*>(&sxp[warp][kk][0]);
            ull xn = *reinterpret_cast<const ull*>(&sxn[warp][kk][0]);
            ull x1 = *reinterpret_cast<const ull*>(&sx1[warp][kk][0]);
            ull x2 = *reinterpret_cast<const ull*>(&sx2[warp][kk][0]);
            oPa = fma2(xp, wa, oPa); oPb = fma2(xp, wb, oPb);
            oNa = fma2(xn, wa, oNa); oNb = fma2(xn, wb, oNb);
            o1a = fma2(x1, wa, o1a); o1b = fma2(x1, wb, o1b);
            o2a = fma2(x2, wa, o2a); o2b = fma2(x2, wb, o2b);
        }
        float opa[2], opb[2], ona[2], onb[2], m1a[2], m1b[2], m2a[2], m2b[2];
        unpack2(oPa, opa[0], opa[1]); unpack2(oPb, opb[0], opb[1]);
        unpack2(oNa, ona[0], ona[1]); unpack2(oNb, onb[0], onb[1]);
        unpack2(o1a, m1a[0], m1a[1]); unpack2(o1b, m1b[0], m1b[1]);
        unpack2(o2a, m2a[0], m2a[1]); unpack2(o2b, m2b[0], m2b[1]);
#pragma unroll
        for (int j = 0; j < 2; j++) {
            int node = nb + j;
            if (node < n) {
                reinterpret_cast<__half2*>(g_hpos16)[(size_t)node * 32 + lane] =
                    __floats2half2_rn(fmaxf(opa[j], 0.f), fmaxf(opb[j], 0.f));
                reinterpret_cast<__half2*>(g_hneg16)[(size_t)node * 32 + lane] =
                    __floats2half2_rn(fmaxf(ona[j], 0.f), fmaxf(onb[j], 0.f));
                if (k1d[j]) { A10 += (double)fmaxf(m1a[j], 0.f); A11 += (double)fmaxf(m1b[j], 0.f); }
                if (k2d[j]) { A20 += (double)fmaxf(m2a[j], 0.f); A21 += (double)fmaxf(m2b[j], 0.f); }
            }
        }
        __syncwarp();
    }
    atomicAdd(&sSum[2 * lane], A10);
    atomicAdd(&sSum[2 * lane + 1], A11);
    atomicAdd(&sSum[64 + 2 * lane], A20);
    atomicAdd(&sSum[64 + 2 * lane + 1], A21);
    __syncthreads();
    if (tid < 128) {
        double v = sSum[tid];
        if (v != 0.0) atomicAdd(&g_summary[tid], v);
    }

    if (tid == 0) {
        __threadfence();
        sLast = (atomicAdd(&g_ctrMega, 1u) == gridDim.x - 1);
    }
    __syncthreads();
    if (sLast) {
        __shared__ float ss[2][64];
        if (tid < 128) {
            double s = g_summary[tid] / (double)k;
            ss[tid >> 6][tid & 63] = (float)(1.0 / (1.0 + exp(-s)));
        }
        __syncthreads();
        if (tid < 128) {
            int p = tid >> 6, c = tid & 63;
            float v = 0.f;
#pragma unroll
            for (int b = 0; b < 64; b++) v += Wdisc[c * 64 + b] * ss[p][b];
            g_v[p][c] = v;
        }
        if (tid == 0) g_ctrMega = 0;
    }
}

// ============================================================================
// Kernel 4: BCE losses (streams fp16 h); last block writes final output.
// ============================================================================

__global__ __launch_bounds__(256)
void loss_kernel(float* __restrict__ out, int n) {
    __shared__ float sv0[64], sv1[64];
    __shared__ double sL[4];
    __shared__ int sLast;
    int tid = threadIdx.x;
    if (tid < 64) { sv0[tid] = g_v[0][tid]; sv1[tid] = g_v[1][tid]; }
    if (tid < 4) sL[tid] = 0.0;
    __syncthreads();
    int warp = tid >> 5, lane = tid & 31;
    float v00 = sv0[2 * lane], v01 = sv0[2 * lane + 1];
    float v10 = sv1[2 * lane], v11 = sv1[2 * lane + 1];
    double l0 = 0, l1 = 0, l2 = 0, l3 = 0;
    const __half2* HP = reinterpret_cast<const __half2*>(g_hpos16);
    const __half2* HN = reinterpret_cast<const __half2*>(g_hneg16);
    for (int node = blockIdx.x * 8 + warp; node < n; node += gridDim.x * 8) {
        float2 hp = __half22float2(HP[(size_t)node * 32 + lane]);
        float2 hn = __half22float2(HN[(size_t)node * 32 + lane]);
        float p1 = hp.x * v00 + hp.y * v01;
        float p2 = hp.x * v10 + hp.y * v11;
        float q1 = hn.x * v00 + hn.y * v01;
        float q2 = hn.x * v10 + hn.y * v11;
#pragma unroll
        for (int off = 16; off; off >>= 1) {
            p1 += __shfl_down_sync(0xffffffffu, p1, off);
            p2 += __shfl_down_sync(0xffffffffu, p2, off);
            q1 += __shfl_down_sync(0xffffffffu, q1, off);
            q2 += __shfl_down_sync(0xffffffffu, q2, off);
        }
        if (lane == 0) {
            l0 += (double)softplusf(-p1);
            l1 += (double)softplusf(q1);
            l2 += (double)softplusf(-p2);
            l3 += (double)softplusf(q2);
        }
    }
    if (lane == 0) {
        atomicAdd(&sL[0], l0); atomicAdd(&sL[1], l1);
        atomicAdd(&sL[2], l2); atomicAdd(&sL[3], l3);
    }
    __syncthreads();
    if (tid < 4) atomicAdd(&g_loss[tid], sL[tid]);

    if (tid == 0) {
        __threadfence();
        sLast = (atomicAdd(&g_ctrLoss, 1u) == gridDim.x - 1);
    }
    __syncthreads();
    if (sLast && tid == 0) {
        out[0] = (float)((g_loss[0] + g_loss[1] + g_loss[2] + g_loss[3]) / (double)n);
        g_ctrLoss = 0;
    }
}

// ============================================================================
// launch
// ============================================================================

extern "C" void kernel_launch(void* const* d_in, const int* in_sizes, int n_in,
                              void* d_out, int out_size) {
    const float* feat = (const float*)d_in[0];
    const float* Wenc = (const float*)d_in[1];
    const float* Wdisc = (const float*)d_in[2];
    const int* src = (const int*)d_in[3];
    const int* dst = (const int*)d_in[4];
    const int* permneg = (const int*)d_in[5];
    const int* perm1 = (const int*)d_in[6];
    const int* perm2 = (const int*)d_in[7];

    int e = in_sizes[3];
    int n = in_sizes[5];
    int k = (int)((double)n * 0.8);

    csr_kernel<<<CSRB, 1024>>>(feat, src, dst, permneg, e, n);
    bfs_dual_kernel<<<BFSB, 1024>>>(perm1, perm2, n, k);

    int mGrid = (n + 15) / 16;
    if (mGrid > 1480) mGrid = 1480;
    mega_gcn_kernel<<<mGrid, 256>>>(Wenc, Wdisc, n, k);

    int lGrid = (n + 7) / 8;
    if (lGrid > 1480) lGrid = 1480;
    loss_kernel<<<lGrid, 256>>>((float*)d_out, n);
}

// round 13
// speedup vs baseline: 1.0471x; 1.0471x over previous
#include <cuda_runtime.h>
#include <cuda_fp16.h>
#include <cooperative_groups.h>
#include <math.h>

namespace cg = cooperative_groups;

// ============================================================================
// DGISubgraphCL — 5-launch pipeline (R9 shape, fp16-aggregation mega):
//   csr (dual CSR + fp16 feat + permuted neg feat) -> dual frontier-BFS +
//   top-k -> annotate (warp/node: keep bits into colD + inv degrees) ->
//   mega GCN (4 streams, fp16 HADD2/HFMA2 aggregation, f32x2 GEMV
//   2 nodes/warp, static smem; last block computes v) -> loss (fp16 h).
// ============================================================================

#define N_MAX 131072
#define E_MAX (N_MAX * 17)
#define HIST_BINS 15001
#define CSRB 264
#define BFSB 132
#define GB 66
#define MAX_SWEEPS 250

typedef unsigned long long ull;

// ---- device scratch ----
__device__ int g_rowD[N_MAX + 1], g_cntD[N_MAX], g_curD[N_MAX];
__device__ int g_rowS[N_MAX + 1], g_cntS[N_MAX], g_curS[N_MAX];
__device__ unsigned g_colD[E_MAX];          // after annotate: s | k1<<30 | k2<<31
__device__ int g_colS[E_MAX];
__device__ __half g_feat16[(size_t)N_MAX * 64];
__device__ __half g_featneg16[(size_t)N_MAX * 64];
__device__ float g_inv1[N_MAX], g_inv2[N_MAX], g_invd[N_MAX];
__device__ int g_hopG[2][N_MAX];
__device__ int g_front[2][2][N_MAX];
__device__ int g_invpermG[2][N_MAX];
__device__ int g_histG[2][HIST_BINS];
__device__ int g_szHist[2][MAX_SWEEPS + 8];
__device__ unsigned char g_keep1[N_MAX];
__device__ unsigned char g_keep2[N_MAX];
__device__ __half g_hpos16[(size_t)N_MAX * 64];
__device__ __half g_hneg16[(size_t)N_MAX * 64];
__device__ double g_summary[128];
__device__ float g_v[2][64];
__device__ double g_loss[4];

__device__ int g_bsD[CSRB], g_bsS[CSRB], g_offD[CSRB], g_offS[CSRB];
__device__ int g_blkCntG[2][GB];
__device__ unsigned long long g_seedkeyG[2];
__device__ int g_hstarG[2], g_rremG[2], g_pstarG[2], g_pselBlockG[2], g_pselRemG[2];

__device__ unsigned g_barC = 0;
__device__ unsigned g_barG[2] = {0, 0};
__device__ unsigned g_ctrMega = 0;
__device__ unsigned g_ctrLoss = 0;

// ============================================================================
// helpers
// ============================================================================

__device__ __forceinline__ ull pack2(float x, float y) {
    ull r; asm("mov.b64 %0, {%1, %2};" : "=l"(r) : "f"(x), "f"(y)); return r;
}
__device__ __forceinline__ void unpack2(ull v, float& x, float& y) {
    asm("mov.b64 {%0, %1}, %2;" : "=f"(x), "=f"(y) : "l"(v));
}
__device__ __forceinline__ ull fma2(ull a, ull b, ull c) {
    ull d; asm("fma.rn.f32x2 %0, %1, %2, %3;" : "=l"(d) : "l"(a), "l"(b), "l"(c)); return d;
}
__device__ __forceinline__ __half2 u2h2(unsigned u) {
    __half2 h; *reinterpret_cast<unsigned*>(&h) = u; return h;
}

__device__ __forceinline__ void xsync(unsigned* ctr, unsigned nblk, unsigned& epoch) {
    __syncthreads();
    if (threadIdx.x == 0) {
        __threadfence();
        unsigned target = (epoch + 1) * nblk;
        atomicAdd(ctr, 1u);
        while (*((volatile unsigned*)ctr) < target) {}
        __threadfence();
    }
    epoch++;
    __syncthreads();
}

__device__ __forceinline__ void xexit(unsigned* ctr, unsigned nblk, unsigned epoch) {
    __syncthreads();
    if (threadIdx.x == 0) {
        __threadfence();
        unsigned target = (epoch + 1) * nblk;
        if (atomicAdd(ctr, 1u) + 1 == target) *ctr = 0;
    }
}

__device__ __forceinline__ float softplusf(float x) {
    return fmaxf(x, 0.f) + log1pf(expf(-fabsf(x)));
}

__device__ __forceinline__ unsigned long long ullmin2(unsigned long long a, unsigned long long b) {
    return a < b ? a : b;
}

__device__ __forceinline__ int blockScanInc(int v, int* sWarp) {
    int lane = threadIdx.x & 31;
    int wid = threadIdx.x >> 5;
#pragma unroll
    for (int off = 1; off < 32; off <<= 1) {
        int t = __shfl_up_sync(0xffffffffu, v, off);
        if (lane >= off) v += t;
    }
    if (lane == 31) sWarp[wid] = v;
    __syncthreads();
    if (wid == 0) {
        int w = sWarp[lane];
#pragma unroll
        for (int off = 1; off < 32; off <<= 1) {
            int t = __shfl_up_sync(0xffffffffu, w, off);
            if (lane >= off) w += t;
        }
        sWarp[lane] = w;
    }
    __syncthreads();
    return v + (wid ? sWarp[wid - 1] : 0);
}

// ============================================================================
// Kernel 1: dual CSR build + feat->fp16 (+ permuted neg table) + zeroing
// ============================================================================

__global__ __launch_bounds__(1024, 2)
void csr_kernel(const float* __restrict__ feat, const int* __restrict__ src,
                const int* __restrict__ dst, const int* __restrict__ permneg,
                int e, int n) {
    unsigned epoch = 0;
    int gtid = blockIdx.x * 1024 + threadIdx.x;
    int gsz = gridDim.x * 1024;

    for (int i = gtid; i < n; i += gsz) { g_cntD[i] = 0; g_cntS[i] = 0; }
    if (gtid < 4) g_loss[gtid] = 0.0;
    if (gtid < 128) g_summary[gtid] = 0.0;
    if (gtid == 0) { g_rowD[n] = e; g_rowS[n] = e; }
    {
        int tot = n * 32;
        const float2* f2 = reinterpret_cast<const float2*>(feat);
        __half2* h2 = reinterpret_cast<__half2*>(g_feat16);
        for (int i = gtid; i < tot; i += gsz) h2[i] = __float22half2_rn(f2[i]);
    }
    xsync(&g_barC, gridDim.x, epoch);

    for (int i = gtid; i < e; i += gsz) {
        atomicAdd(&g_cntD[dst[i]], 1);
        atomicAdd(&g_cntS[src[i]], 1);
    }
    {
        int warp = gtid >> 5, lane = gtid & 31, nw = gsz >> 5;
        const __half2* fsrc = reinterpret_cast<const __half2*>(g_feat16);
        __half2* fdst = reinterpret_cast<__half2*>(g_featneg16);
        for (int i = warp; i < n; i += nw) {
            int r = __ldg(&permneg[i]);
            fdst[(size_t)i * 32 + lane] = fsrc[(size_t)r * 32 + lane];
        }
    }
    xsync(&g_barC, gridDim.x, epoch);

    __shared__ int sWarp[32];
    __shared__ int sRun, sTot;
    int chunk = (n + gridDim.x - 1) / gridDim.x;
    int b0 = blockIdx.x * chunk;
    int b1 = min(b0 + chunk, n);
    for (int which = 0; which < 2; which++) {
        int* cnt = which ? g_cntS : g_cntD;
        int* row = which ? g_rowS : g_rowD;
        int* bs = which ? g_bsS : g_bsD;
        if (threadIdx.x == 0) sRun = 0;
        __syncthreads();
        for (int base = b0; base < b1; base += 1024) {
            int i = base + threadIdx.x;
            int v = (i < b1) ? __ldcg(&cnt[i]) : 0;
            int incl = blockScanInc(v, sWarp);
            if (i < b1) row[i] = sRun + incl - v;
            if (threadIdx.x == 1023) sTot = incl;
            __syncthreads();
            if (threadIdx.x == 0) sRun += sTot;
            __syncthreads();
        }
        if (threadIdx.x == 0) bs[blockIdx.x] = sRun;
        __syncthreads();
    }
    xsync(&g_barC, gridDim.x, epoch);

    if (blockIdx.x == 0) {
        int b = threadIdx.x;
        int vD = (b < (int)gridDim.x) ? __ldcg(&g_bsD[b]) : 0;
        int incl = blockScanInc(vD, sWarp);
        if (b < (int)gridDim.x) g_offD[b] = incl - vD;
        int vS = (b < (int)gridDim.x) ? __ldcg(&g_bsS[b]) : 0;
        incl = blockScanInc(vS, sWarp);
        if (b < (int)gridDim.x) g_offS[b] = incl - vS;
    }
    xsync(&g_barC, gridDim.x, epoch);

    {
        int oD = __ldcg(&g_offD[blockIdx.x]);
        int oS = __ldcg(&g_offS[blockIdx.x]);
        for (int i = b0 + threadIdx.x; i < b1; i += 1024) {
            int vD = __ldcg(&g_rowD[i]) + oD;
            int vS = __ldcg(&g_rowS[i]) + oS;
            g_rowD[i] = vD; g_curD[i] = vD;
            g_rowS[i] = vS; g_curS[i] = vS;
        }
    }
    xsync(&g_barC, gridDim.x, epoch);

    for (int i = gtid; i < e; i += gsz) {
        int d = dst[i], s = src[i];
        int pd = atomicAdd(&g_curD[d], 1);
        g_colD[pd] = (unsigned)s;
        int ps = atomicAdd(&g_curS[s], 1);
        g_colS[ps] = d;
    }
    xexit(&g_barC, gridDim.x, epoch);
}

// ============================================================================
// Kernel 2: dual frontier-BFS + exact top-k selection (both perms concurrent)
// ============================================================================

__global__ __launch_bounds__(1024, 1)
void bfs_dual_kernel(const int* __restrict__ perm1, const int* __restrict__ perm2, int n, int k) {
    int g = (blockIdx.x < GB) ? 0 : 1;
    int gb = blockIdx.x - g * GB;
    const int* perm = g ? perm2 : perm1;
    unsigned char* keep = g ? g_keep2 : g_keep1;
    int* hop = g_hopG[g];
    int* invp = g_invpermG[g];
    int* hist = g_histG[g];
    unsigned* bar = &g_barG[g];
    unsigned epoch = 0;
    int gtid = gb * 1024 + threadIdx.x;
    int gsz = GB * 1024;
    const int INF = n;

    __shared__ int sWarp[32];
    __shared__ unsigned long long sK[32];

    int root = __ldg(&perm[0]);
    for (int i = gtid; i < n; i += gsz) {
        __stcg(&hop[i], (i == root) ? 0 : INF);
        __stcg(&invp[__ldg(&perm[i])], i);
    }
    for (int i = gtid; i < HIST_BINS; i += gsz) __stcg(&hist[i], 0);
    for (int i = gtid; i < MAX_SWEEPS + 8; i += gsz) __stcg(&g_szHist[g][i], 0);
    if (gtid == 0) {
        __stcg(&g_front[g][0][0], root);
        __stcg(&g_szHist[g][0], 1);
        g_seedkeyG[g] = ~0ull;
    }
    xsync(bar, GB, epoch);

    int cnt = 1;
    int t = 0;
    int lane = threadIdx.x & 31;
    while (cnt <= k && t < MAX_SWEEPS) {
        int fsz = __ldcg(&g_szHist[g][t]);
        const int* fin = g_front[g][t & 1];
        int* fout = g_front[g][(t + 1) & 1];
        int* ctr = &g_szHist[g][t + 1];
        for (int idx = gtid; idx < fsz; idx += gsz) {
            int u = __ldcg(&fin[idx]);
            int s0 = g_rowS[u], s1 = g_rowS[u + 1];
            for (int e2 = s0; e2 < s1; e2++) {
                int v = g_colS[e2];
                bool win = false;
                if (__ldcg(&hop[v]) == INF)
                    win = (atomicCAS(&hop[v], INF, t + 1) == INF);
                if (win) {
                    cg::coalesced_group grp = cg::coalesced_threads();
                    int base;
                    if (grp.thread_rank() == 0) base = atomicAdd(ctr, (int)grp.size());
                    base = grp.shfl(base, 0);
                    __stcg(&fout[base + grp.thread_rank()], v);
                }
            }
        }
        xsync(bar, GB, epoch);
        int newly = __ldcg(&g_szHist[g][t + 1]);
        t += 1;
        cnt += newly;
        if (newly == 0 && cnt <= k) {
            unsigned long long key = ~0ull;
            for (int i = gtid; i < n; i += gsz) {
                if (__ldcg(&hop[i]) == INF)
                    key = ullmin2(key, ((unsigned long long)(unsigned)__ldg(&perm[i]) << 32) | (unsigned)i);
            }
#pragma unroll
            for (int off = 16; off; off >>= 1)
                key = ullmin2(key, __shfl_down_sync(0xffffffffu, key, off));
            int wid = threadIdx.x >> 5;
            if (lane == 0) sK[wid] = key;
            __syncthreads();
            if (threadIdx.x < 32) {
                unsigned long long kk2 = sK[threadIdx.x];
#pragma unroll
                for (int off = 16; off; off >>= 1)
                    kk2 = ullmin2(kk2, __shfl_down_sync(0xffffffffu, kk2, off));
                if (threadIdx.x == 0 && kk2 != ~0ull) atomicMin(&g_seedkeyG[g], kk2);
            }
            xsync(bar, GB, epoch);
            if (gtid == 0) {
                unsigned long long kv = g_seedkeyG[g];
                int idx = (int)(unsigned)(kv & 0xffffffffull);
                __stcg(&hop[idx], t);
                __stcg(&g_front[g][t & 1][0], idx);
                __stcg(&g_szHist[g][t], 1);
                g_seedkeyG[g] = ~0ull;
            }
            cnt += 1;
            xsync(bar, GB, epoch);
        }
    }

    {
        __shared__ int sh[256];
        for (int j = threadIdx.x; j < 256; j += 1024) sh[j] = 0;
        __syncthreads();
        for (int i = gtid; i < n; i += gsz) {
            int hv = min(__ldcg(&hop[i]), 15000);
            if (hv < 256) atomicAdd(&sh[hv], 1);
            else atomicAdd(&hist[hv], 1);
        }
        __syncthreads();
        for (int j = threadIdx.x; j < 256; j += 1024)
            if (sh[j]) atomicAdd(&hist[j], sh[j]);
    }
    xsync(bar, GB, epoch);

    if (gb == 0) {
        __shared__ int sRun, sTot, sDone;
        if (threadIdx.x == 0) { sRun = 0; sDone = 0; }
        __syncthreads();
        for (int base = 0; base < HIST_BINS; base += 1024) {
            if (sDone) break;
            int h = base + threadIdx.x;
            int v = (h < HIST_BINS) ? __ldcg(&hist[h]) : 0;
            int incl = blockScanInc(v, sWarp);
            int P = sRun + incl;
            if (v > 0 && P >= k && P - v < k) { g_hstarG[g] = h; g_rremG[g] = k - (P - v); sDone = 1; }
            if (threadIdx.x == 1023) sTot = incl;
            __syncthreads();
            if (threadIdx.x == 0) sRun += sTot;
            __syncthreads();
        }
    }
    xsync(bar, GB, epoch);
    int hstar = *(volatile int*)&g_hstarG[g];
    int rrem = *(volatile int*)&g_rremG[g];

    int chunk = (n + GB - 1) / GB;
    int v0 = gb * chunk, v1 = min(v0 + chunk, n);
    {
        int c = 0;
        for (int v = v0 + threadIdx.x; v < v1; v += 1024) {
            int j = __ldcg(&invp[v]);
            c += (min(__ldcg(&hop[j]), 15000) == hstar);
        }
#pragma unroll
        for (int off = 16; off; off >>= 1) c += __shfl_down_sync(0xffffffffu, c, off);
        int wid = threadIdx.x >> 5;
        if (lane == 0) sWarp[wid] = c;
        __syncthreads();
        if (threadIdx.x < 32) {
            int r = sWarp[threadIdx.x];
#pragma unroll
            for (int off = 16; off; off >>= 1) r += __shfl_down_sync(0xffffffffu, r, off);
            if (threadIdx.x == 0) g_blkCntG[g][gb] = r;
        }
    }
    xsync(bar, GB, epoch);
    if (gb == 0) {
        int b = threadIdx.x;
        int v = (b < GB) ? __ldcg(&g_blkCntG[g][b]) : 0;
        int incl = blockScanInc(v, sWarp);
        int excl = incl - v;
        if (b < GB && v > 0 && excl < rrem && rrem <= incl) {
            g_pselBlockG[g] = b; g_pselRemG[g] = rrem - excl;
        }
    }
    xsync(bar, GB, epoch);
    if (gb == *(volatile int*)&g_pselBlockG[g]) {
        int rem = *(volatile int*)&g_pselRemG[g];
        __shared__ int sRun2, sTot2, sDone2;
        if (threadIdx.x == 0) { sRun2 = 0; sDone2 = 0; }
        __syncthreads();
        for (int base = v0; base < v1; base += 1024) {
            if (sDone2) break;
            int v = base + threadIdx.x;
            int pred = 0;
            if (v < v1) {
                int j = __ldcg(&invp[v]);
                pred = (min(__ldcg(&hop[j]), 15000) == hstar);
            }
            int incl = blockScanInc(pred, sWarp);
            int cum = sRun2 + incl;
            if (pred && cum == rem) { g_pstarG[g] = v; sDone2 = 1; }
            if (threadIdx.x == 1023) sTot2 = incl;
            __syncthreads();
            if (threadIdx.x == 0) sRun2 += sTot2;
            __syncthreads();
        }
    }
    xsync(bar, GB, epoch);
    int pstar = *(volatile int*)&g_pstarG[g];
    for (int i = gtid; i < n; i += gsz) {
        int hv = min(__ldcg(&hop[i]), 15000);
        keep[i] = (hv < hstar) || (hv == hstar && __ldg(&perm[i]) <= pstar);
    }
    xexit(bar, GB, epoch);
}

// ============================================================================
// Kernel 3: annotate (warp per node): keep bits into colD + counts/inverses.
// ============================================================================

__global__ __launch_bounds__(256)
void annotate_kernel(int n) {
    int lane = threadIdx.x & 31;
    int warpId = (blockIdx.x * 256 + threadIdx.x) >> 5;
    int nW = gridDim.x * 8;
    for (int node = warpId; node < n; node += nW) {
        int s0 = g_rowD[node], s1 = g_rowD[node + 1];
        int c1 = 0, c2 = 0;
        for (int e = s0 + lane; e < s1; e += 32) {
            unsigned c = g_colD[e] & 0x3FFFFFFFu;
            unsigned k1 = (unsigned)__ldg(&g_keep1[c]);
            unsigned k2 = (unsigned)__ldg(&g_keep2[c]);
            g_colD[e] = c | (k1 << 30) | (k2 << 31);
            c1 += (int)k1; c2 += (int)k2;
        }
#pragma unroll
        for (int off = 16; off; off >>= 1) {
            c1 += __shfl_down_sync(0xffffffffu, c1, off);
            c2 += __shfl_down_sync(0xffffffffu, c2, off);
        }
        if (lane == 0) {
            g_inv1[node] = 1.f / (float)max(c1, 1);
            g_inv2[node] = 1.f / (float)max(c2, 1);
            g_invd[node] = 1.f / (float)max(s1 - s0, 1);
        }
    }
}

// ============================================================================
// Kernel 4: mega GCN — fp16 aggregation of 4 streams (HADD2/HFMA2), f32x2
// GEMV 2 nodes/warp, static smem; LAST block computes v.
// ============================================================================

#define MEGA_EDGE(cc)                                                          \
    do {                                                                       \
        unsigned s_ = (cc) & 0x3FFFFFFFu;                                      \
        __half2 f_ = FP[(size_t)s_ * 32 + lane];                               \
        __half2 g_ = FN[(size_t)s_ * 32 + lane];                               \
        aP = __hadd2(aP, f_);                                                  \
        aN = __hadd2(aN, g_);                                                  \
        unsigned b1_ = (unsigned)(((int)((cc) << 1)) >> 31) & 0x3C003C00u;     \
        unsigned b2_ = (unsigned)(((int)(cc)) >> 31) & 0x3C003C00u;            \
        aM1 = __hfma2(f_, u2h2(b1_), aM1);                                     \
        aM2 = __hfma2(f_, u2h2(b2_), aM2);                                     \
    } while (0)

__global__ __launch_bounds__(256)
void mega_gcn_kernel(const float* __restrict__ Wenc, const float* __restrict__ Wdisc,
                     int n, int k) {
    __shared__ float sW[4096];
    __shared__ __align__(8) float sxp[8][64][2];
    __shared__ __align__(8) float sxn[8][64][2];
    __shared__ __align__(8) float sx1[8][64][2];
    __shared__ __align__(8) float sx2[8][64][2];
    __shared__ double sSum[128];
    __shared__ int sLast;
    int tid = threadIdx.x;
    for (int j = tid; j < 4096; j += 256) sW[j] = Wenc[j];
    if (tid < 128) sSum[tid] = 0.0;
    __syncthreads();
    int warp = tid >> 5, lane = tid & 31;
    double A10 = 0.0, A11 = 0.0, A20 = 0.0, A21 = 0.0;
    const __half2* FP = reinterpret_cast<const __half2*>(g_feat16);
    const __half2* FN = reinterpret_cast<const __half2*>(g_featneg16);

    for (int nb = (blockIdx.x * 8 + warp) * 2; nb < n; nb += gridDim.x * 16) {
        int k1d[2], k2d[2];
#pragma unroll
        for (int j = 0; j < 2; j++) {
            int node = nb + j;
            bool valid = node < n;
            k1d[j] = valid ? (int)g_keep1[node] : 0;
            k2d[j] = valid ? (int)g_keep2[node] : 0;
            int s0 = valid ? g_rowD[node] : 0;
            int s1 = valid ? g_rowD[node + 1] : 0;

            __half2 aP = u2h2(0), aN = u2h2(0), aM1 = u2h2(0), aM2 = u2h2(0);

            int e2 = s0;
            while (e2 < s1 && (e2 & 3)) { MEGA_EDGE(__ldcs(&g_colD[e2])); e2++; }
            for (; e2 + 4 <= s1; e2 += 4) {
                uint4 c4 = *reinterpret_cast<const uint4*>(&g_colD[e2]);
                MEGA_EDGE(c4.x); MEGA_EDGE(c4.y); MEGA_EDGE(c4.z); MEGA_EDGE(c4.w);
            }
            while (e2 < s1) { MEGA_EDGE(__ldcs(&g_colD[e2])); e2++; }

            float invd = valid ? __ldg(&g_invd[node]) : 1.f;
            float i1 = valid ? __ldg(&g_inv1[node]) : 1.f;
            float i2 = valid ? __ldg(&g_inv2[node]) : 1.f;
            float2 P = __half22float2(aP), Q = __half22float2(aN);
            float2 M1 = __half22float2(aM1), M2 = __half22float2(aM2);
            sxp[warp][2 * lane][j] = P.x * invd; sxp[warp][2 * lane + 1][j] = P.y * invd;
            sxn[warp][2 * lane][j] = Q.x * invd; sxn[warp][2 * lane + 1][j] = Q.y * invd;
            sx1[warp][2 * lane][j] = M1.x * i1;  sx1[warp][2 * lane + 1][j] = M1.y * i1;
            sx2[warp][2 * lane][j] = M2.x * i2;  sx2[warp][2 * lane + 1][j] = M2.y * i2;
        }
        __syncwarp();

        // f32x2 packed GEMV: each ull accumulator = (node0, node1)
        ull oPa = 0, oPb = 0, oNa = 0, oNb = 0;
        ull o1a = 0, o1b = 0, o2a = 0, o2b = 0;
#pragma unroll 16
        for (int kk = 0; kk < 64; kk++) {
            float2 w = *reinterpret_cast<const float2*>(&sW[kk * 64 + 2 * lane]);
            ull wa = pack2(w.x, w.x);
            ull wb = pack2(w.y, w.y);
            ull xp = *reinterpret_cast<const ull*>(&sxp[warp][kk][0]);
            ull xn = *reinterpret_cast<const ull*>(&sxn[warp][kk][0]);
            ull x1 = *reinterpret_cast<const ull*>(&sx1[warp][kk][0]);
            ull x2 = *reinterpret_cast<const ull*>(&sx2[warp][kk][0]);
            oPa = fma2(xp, wa, oPa); oPb = fma2(xp, wb, oPb);
            oNa = fma2(xn, wa, oNa); oNb = fma2(xn, wb, oNb);
            o1a = fma2(x1, wa, o1a); o1b = fma2(x1, wb, o1b);
            o2a = fma2(x2, wa, o2a); o2b = fma2(x2, wb, o2b);
        }
        float opa[2], opb[2], ona[2], onb[2], m1a[2], m1b[2], m2a[2], m2b[2];
        unpack2(oPa, opa[0], opa[1]); unpack2(oPb, opb[0], opb[1]);
        unpack2(oNa, ona[0], ona[1]); unpack2(oNb, onb[0], onb[1]);
        unpack2(o1a, m1a[0], m1a[1]); unpack2(o1b, m1b[0], m1b[1]);
        unpack2(o2a, m2a[0], m2a[1]); unpack2(o2b, m2b[0], m2b[1]);
#pragma unroll
        for (int j = 0; j < 2; j++) {
            int node = nb + j;
            if (node < n) {
                reinterpret_cast<__half2*>(g_hpos16)[(size_t)node * 32 + lane] =
                    __floats2half2_rn(fmaxf(opa[j], 0.f), fmaxf(opb[j], 0.f));
                reinterpret_cast<__half2*>(g_hneg16)[(size_t)node * 32 + lane] =
                    __floats2half2_rn(fmaxf(ona[j], 0.f), fmaxf(onb[j], 0.f));
                if (k1d[j]) { A10 += (double)fmaxf(m1a[j], 0.f); A11 += (double)fmaxf(m1b[j], 0.f); }
                if (k2d[j]) { A20 += (double)fmaxf(m2a[j], 0.f); A21 += (double)fmaxf(m2b[j], 0.f); }
            }
        }
        __syncwarp();
    }
    atomicAdd(&sSum[2 * lane], A10);
    atomicAdd(&sSum[2 * lane + 1], A11);
    atomicAdd(&sSum[64 + 2 * lane], A20);
    atomicAdd(&sSum[64 + 2 * lane + 1], A21);
    __syncthreads();
    if (tid < 128) {
        double v = sSum[tid];
        if (v != 0.0) atomicAdd(&g_summary[tid], v);
    }

    if (tid == 0) {
        __threadfence();
        sLast = (atomicAdd(&g_ctrMega, 1u) == gridDim.x - 1);
    }
    __syncthreads();
    if (sLast) {
        __shared__ float ss[2][64];
        if (tid < 128) {
            double s = g_summary[tid] / (double)k;
            ss[tid >> 6][tid & 63] = (float)(1.0 / (1.0 + exp(-s)));
        }
        __syncthreads();
        if (tid < 128) {
            int p = tid >> 6, c = tid & 63;
            float v = 0.f;
#pragma unroll
            for (int b = 0; b < 64; b++) v += Wdisc[c * 64 + b] * ss[p][b];
            g_v[p][c] = v;
        }
        if (tid == 0) g_ctrMega = 0;
    }
}

// ============================================================================
// Kernel 5: BCE losses (streams fp16 h); last block writes final output.
// ============================================================================

__global__ __launch_bounds__(256)
void loss_kernel(float* __restrict__ out, int n) {
    __shared__ float sv0[64], sv1[64];
    __shared__ double sL[4];
    __shared__ int sLast;
    int tid = threadIdx.x;
    if (tid < 64) { sv0[tid] = g_v[0][tid]; sv1[tid] = g_v[1][tid]; }
    if (tid < 4) sL[tid] = 0.0;
    __syncthreads();
    int warp = tid >> 5, lane = tid & 31;
    float v00 = sv0[2 * lane], v01 = sv0[2 * lane + 1];
    float v10 = sv1[2 * lane], v11 = sv1[2 * lane + 1];
    double l0 = 0, l1 = 0, l2 = 0, l3 = 0;
    const __half2* HP = reinterpret_cast<const __half2*>(g_hpos16);
    const __half2* HN = reinterpret_cast<const __half2*>(g_hneg16);
    for (int node = blockIdx.x * 8 + warp; node < n; node += gridDim.x * 8) {
        float2 hp = __half22float2(HP[(size_t)node * 32 + lane]);
        float2 hn = __half22float2(HN[(size_t)node * 32 + lane]);
        float p1 = hp.x * v00 + hp.y * v01;
        float p2 = hp.x * v10 + hp.y * v11;
        float q1 = hn.x * v00 + hn.y * v01;
        float q2 = hn.x * v10 + hn.y * v11;
#pragma unroll
        for (int off = 16; off; off >>= 1) {
            p1 += __shfl_down_sync(0xffffffffu, p1, off);
            p2 += __shfl_down_sync(0xffffffffu, p2, off);
            q1 += __shfl_down_sync(0xffffffffu, q1, off);
            q2 += __shfl_down_sync(0xffffffffu, q2, off);
        }
        if (lane == 0) {
            l0 += (double)softplusf(-p1);
            l1 += (double)softplusf(q1);
            l2 += (double)softplusf(-p2);
            l3 += (double)softplusf(q2);
        }
    }
    if (lane == 0) {
        atomicAdd(&sL[0], l0); atomicAdd(&sL[1], l1);
        atomicAdd(&sL[2], l2); atomicAdd(&sL[3], l3);
    }
    __syncthreads();
    if (tid < 4) atomicAdd(&g_loss[tid], sL[tid]);

    if (tid == 0) {
        __threadfence();
        sLast = (atomicAdd(&g_ctrLoss, 1u) == gridDim.x - 1);
    }
    __syncthreads();
    if (sLast && tid == 0) {
        out[0] = (float)((g_loss[0] + g_loss[1] + g_loss[2] + g_loss[3]) / (double)n);
        g_ctrLoss = 0;
    }
}

// ============================================================================
// launch
// ============================================================================

extern "C" void kernel_launch(void* const* d_in, const int* in_sizes, int n_in,
                              void* d_out, int out_size) {
    const float* feat = (const float*)d_in[0];
    const float* Wenc = (const float*)d_in[1];
    const float* Wdisc = (const float*)d_in[2];
    const int* src = (const int*)d_in[3];
    const int* dst = (const int*)d_in[4];
    const int* permneg = (const int*)d_in[5];
    const int* perm1 = (const int*)d_in[6];
    const int* perm2 = (const int*)d_in[7];

    int e = in_sizes[3];
    int n = in_sizes[5];
    int k = (int)((double)n * 0.8);

    csr_kernel<<<CSRB, 1024>>>(feat, src, dst, permneg, e, n);
    bfs_dual_kernel<<<BFSB, 1024>>>(perm1, perm2, n, k);

    int aGrid = (n + 7) / 8;
    if (aGrid > 1480) aGrid = 1480;
    annotate_kernel<<<aGrid, 256>>>(n);

    int mGrid = (n + 15) / 16;
    if (mGrid > 1480) mGrid = 1480;
    mega_gcn_kernel<<<mGrid, 256>>>(Wenc, Wdisc, n, k);

    int lGrid = (n + 7) / 8;
    if (lGrid > 1480) lGrid = 1480;
    loss_kernel<<<lGrid, 256>>>((float*)d_out, n);
}

// round 15
// speedup vs baseline: 1.2360x; 1.1805x over previous
#include <cuda_runtime.h>
#include <cuda_fp16.h>
#include <cooperative_groups.h>
#include <math.h>

namespace cg = cooperative_groups;

// ============================================================================
// DGISubgraphCL — 5-launch pipeline:
//   csr (dst-CSR ONLY + fp16 feat + permuted neg feat) ->
//   bfs_dual (PULL frontier BFS on dst-CSR + exact top-k, both perms) ->
//   annotate (warp/node: keep bits into colD + inv degrees) ->
//   mega GCN (4 streams, fp16 HADD2/HFMA2 aggregation, f32x2 GEMV
//   2 nodes/warp; last block computes v) -> loss (fp16 h).
// ============================================================================

#define N_MAX 131072
#define E_MAX (N_MAX * 17)
#define HIST_BINS 15001
#define CSRB 264
#define BFSB 132
#define GB 66
#define MAX_SWEEPS 250

typedef unsigned long long ull;

// ---- device scratch ----
__device__ int g_rowD[N_MAX + 1], g_cntD[N_MAX], g_curD[N_MAX];
__device__ unsigned g_colD[E_MAX];          // after annotate: s | k1<<30 | k2<<31
__device__ __half g_feat16[(size_t)N_MAX * 64];
__device__ __half g_featneg16[(size_t)N_MAX * 64];
__device__ float g_inv1[N_MAX], g_inv2[N_MAX], g_invd[N_MAX];
__device__ int g_hopG[2][N_MAX];
__device__ int g_front[2][2][N_MAX];        // unvisited lists (double buffered)
__device__ int g_invpermG[2][N_MAX];
__device__ int g_histG[2][HIST_BINS];
__device__ int g_szHist[2][MAX_SWEEPS + 8]; // [0]=initial unvisited size; [t+1]=append ctr
__device__ unsigned char g_keep1[N_MAX];
__device__ unsigned char g_keep2[N_MAX];
__device__ __half g_hpos16[(size_t)N_MAX * 64];
__device__ __half g_hneg16[(size_t)N_MAX * 64];
__device__ double g_summary[128];
__device__ float g_v[2][64];
__device__ double g_loss[4];

__device__ int g_bsD[CSRB], g_offD[CSRB];
__device__ int g_blkCntG[2][GB];
__device__ unsigned long long g_seedkeyG[2];
__device__ int g_hstarG[2], g_rremG[2], g_pstarG[2], g_pselBlockG[2], g_pselRemG[2];

__device__ unsigned g_barC = 0;
__device__ unsigned g_barG[2] = {0, 0};
__device__ unsigned g_ctrMega = 0;
__device__ unsigned g_ctrLoss = 0;

// ============================================================================
// helpers
// ============================================================================

__device__ __forceinline__ ull pack2(float x, float y) {
    ull r; asm("mov.b64 %0, {%1, %2};" : "=l"(r) : "f"(x), "f"(y)); return r;
}
__device__ __forceinline__ void unpack2(ull v, float& x, float& y) {
    asm("mov.b64 {%0, %1}, %2;" : "=f"(x), "=f"(y) : "l"(v));
}
__device__ __forceinline__ ull fma2(ull a, ull b, ull c) {
    ull d; asm("fma.rn.f32x2 %0, %1, %2, %3;" : "=l"(d) : "l"(a), "l"(b), "l"(c)); return d;
}
__device__ __forceinline__ __half2 u2h2(unsigned u) {
    __half2 h; *reinterpret_cast<unsigned*>(&h) = u; return h;
}

__device__ __forceinline__ void xsync(unsigned* ctr, unsigned nblk, unsigned& epoch) {
    __syncthreads();
    if (threadIdx.x == 0) {
        __threadfence();
        unsigned target = (epoch + 1) * nblk;
        atomicAdd(ctr, 1u);
        while (*((volatile unsigned*)ctr) < target) {}
        __threadfence();
    }
    epoch++;
    __syncthreads();
}

__device__ __forceinline__ void xexit(unsigned* ctr, unsigned nblk, unsigned epoch) {
    __syncthreads();
    if (threadIdx.x == 0) {
        __threadfence();
        unsigned target = (epoch + 1) * nblk;
        if (atomicAdd(ctr, 1u) + 1 == target) *ctr = 0;
    }
}

__device__ __forceinline__ float softplusf(float x) {
    return fmaxf(x, 0.f) + log1pf(expf(-fabsf(x)));
}

__device__ __forceinline__ unsigned long long ullmin2(unsigned long long a, unsigned long long b) {
    return a < b ? a : b;
}

__device__ __forceinline__ int blockScanInc(int v, int* sWarp) {
    int lane = threadIdx.x & 31;
    int wid = threadIdx.x >> 5;
#pragma unroll
    for (int off = 1; off < 32; off <<= 1) {
        int t = __shfl_up_sync(0xffffffffu, v, off);
        if (lane >= off) v += t;
    }
    if (lane == 31) sWarp[wid] = v;
    __syncthreads();
    if (wid == 0) {
        int w = sWarp[lane];
#pragma unroll
        for (int off = 1; off < 32; off <<= 1) {
            int t = __shfl_up_sync(0xffffffffu, w, off);
            if (lane >= off) w += t;
        }
        sWarp[lane] = w;
    }
    __syncthreads();
    return v + (wid ? sWarp[wid - 1] : 0);
}

// ============================================================================
// Kernel 1: dst-CSR build + feat->fp16 (+ permuted neg table) + zeroing
// ============================================================================

__global__ __launch_bounds__(1024, 2)
void csr_kernel(const float* __restrict__ feat, const int* __restrict__ src,
                const int* __restrict__ dst, const int* __restrict__ permneg,
                int e, int n) {
    unsigned epoch = 0;
    int gtid = blockIdx.x * 1024 + threadIdx.x;
    int gsz = gridDim.x * 1024;

    for (int i = gtid; i < n; i += gsz) g_cntD[i] = 0;
    if (gtid < 4) g_loss[gtid] = 0.0;
    if (gtid < 128) g_summary[gtid] = 0.0;
    if (gtid == 0) g_rowD[n] = e;
    {
        int tot = n * 32;
        const float2* f2 = reinterpret_cast<const float2*>(feat);
        __half2* h2 = reinterpret_cast<__half2*>(g_feat16);
        for (int i = gtid; i < tot; i += gsz) h2[i] = __float22half2_rn(f2[i]);
    }
    xsync(&g_barC, gridDim.x, epoch);

    // count in-degrees + build permuted neg feature table
    for (int i = gtid; i < e; i += gsz) atomicAdd(&g_cntD[dst[i]], 1);
    {
        int warp = gtid >> 5, lane = gtid & 31, nw = gsz >> 5;
        const __half2* fsrc = reinterpret_cast<const __half2*>(g_feat16);
        __half2* fdst = reinterpret_cast<__half2*>(g_featneg16);
        for (int i = warp; i < n; i += nw) {
            int r = __ldg(&permneg[i]);
            fdst[(size_t)i * 32 + lane] = fsrc[(size_t)r * 32 + lane];
        }
    }
    xsync(&g_barC, gridDim.x, epoch);

    // per-block exclusive scan of cntD into rowD
    __shared__ int sWarp[32];
    __shared__ int sRun, sTot;
    int chunk = (n + gridDim.x - 1) / gridDim.x;
    int b0 = blockIdx.x * chunk;
    int b1 = min(b0 + chunk, n);
    if (threadIdx.x == 0) sRun = 0;
    __syncthreads();
    for (int base = b0; base < b1; base += 1024) {
        int i = base + threadIdx.x;
        int v = (i < b1) ? __ldcg(&g_cntD[i]) : 0;
        int incl = blockScanInc(v, sWarp);
        if (i < b1) g_rowD[i] = sRun + incl - v;
        if (threadIdx.x == 1023) sTot = incl;
        __syncthreads();
        if (threadIdx.x == 0) sRun += sTot;
        __syncthreads();
    }
    if (threadIdx.x == 0) g_bsD[blockIdx.x] = sRun;
    xsync(&g_barC, gridDim.x, epoch);

    if (blockIdx.x == 0) {
        int b = threadIdx.x;
        int vD = (b < (int)gridDim.x) ? __ldcg(&g_bsD[b]) : 0;
        int incl = blockScanInc(vD, sWarp);
        if (b < (int)gridDim.x) g_offD[b] = incl - vD;
    }
    xsync(&g_barC, gridDim.x, epoch);

    {
        int oD = __ldcg(&g_offD[blockIdx.x]);
        for (int i = b0 + threadIdx.x; i < b1; i += 1024) {
            int vD = __ldcg(&g_rowD[i]) + oD;
            g_rowD[i] = vD; g_curD[i] = vD;     // cursor starts at row base
        }
    }
    xsync(&g_barC, gridDim.x, epoch);

    // scatter by dst: single atomic gives absolute slot
    for (int i = gtid; i < e; i += gsz) {
        int d = dst[i];
        int pd = atomicAdd(&g_curD[d], 1);
        g_colD[pd] = (unsigned)src[i];
    }
    xexit(&g_barC, gridDim.x, epoch);
}

// ============================================================================
// Kernel 2: dual PULL frontier-BFS on dst-CSR + exact top-k (both perms)
// ============================================================================

__global__ __launch_bounds__(1024, 1)
void bfs_dual_kernel(const int* __restrict__ perm1, const int* __restrict__ perm2, int n, int k) {
    int g = (blockIdx.x < GB) ? 0 : 1;
    int gb = blockIdx.x - g * GB;
    const int* perm = g ? perm2 : perm1;
    unsigned char* keep = g ? g_keep2 : g_keep1;
    int* hop = g_hopG[g];
    int* invp = g_invpermG[g];
    int* hist = g_histG[g];
    unsigned* bar = &g_barG[g];
    unsigned epoch = 0;
    int gtid = gb * 1024 + threadIdx.x;
    int gsz = GB * 1024;
    const int INF = n;

    __shared__ int sWarp[32];
    __shared__ unsigned long long sK[32];

    int root = __ldg(&perm[0]);
    for (int i = gtid; i < n; i += gsz) {
        __stcg(&hop[i], (i == root) ? 0 : INF);
        __stcg(&invp[__ldg(&perm[i])], i);
        if (i != root) __stcg(&g_front[g][0][i - (i > root)], i);  // initial unvisited list
    }
    for (int i = gtid; i < HIST_BINS; i += gsz) __stcg(&hist[i], 0);
    for (int i = gtid; i < MAX_SWEEPS + 8; i += gsz) __stcg(&g_szHist[g][i], 0);
    if (gtid == 0) {
        __stcg(&g_szHist[g][0], n - 1);
        g_seedkeyG[g] = ~0ull;
    }
    xsync(bar, GB, epoch);

    // ---- pull BFS over the unvisited list ----
    // Sweep t+1 marks v iff some in-neighbor has hop == t (exact replica of the
    // reference synchronous min-relaxation). Seeded nodes drop via the
    // hop != INF guard; visited count == n - listsize stays exact.
    int vis = 1;   // visited count entering the sweep (root)
    int usz = n - 1;
    int t = 0;
    int lane = threadIdx.x & 31;
    while (vis <= k && t < MAX_SWEEPS) {
        const int* uin = g_front[g][t & 1];
        int* uout = g_front[g][(t + 1) & 1];
        int* ctr = &g_szHist[g][t + 1];
        for (int idx = gtid; idx < usz; idx += gsz) {
            int v = __ldcg(&uin[idx]);
            if (__ldcg(&hop[v]) != INF) continue;   // seeded last round: drop
            int s0 = g_rowD[v], s1 = g_rowD[v + 1];
            bool found = false;
            int e2 = s0;
            for (; e2 + 4 <= s1; e2 += 4) {
                unsigned c0 = __ldg(&g_colD[e2]);
                unsigned c1 = __ldg(&g_colD[e2 + 1]);
                unsigned c2 = __ldg(&g_colD[e2 + 2]);
                unsigned c3 = __ldg(&g_colD[e2 + 3]);
                int h0 = __ldcg(&hop[c0]);
                int h1 = __ldcg(&hop[c1]);
                int h2 = __ldcg(&hop[c2]);
                int h3 = __ldcg(&hop[c3]);
                if (h0 == t || h1 == t || h2 == t || h3 == t) { found = true; break; }
            }
            if (!found) {
                for (; e2 < s1; e2++) {
                    if (__ldcg(&hop[__ldg(&g_colD[e2])]) == t) { found = true; break; }
                }
            }
            if (found) {
                __stcg(&hop[v], t + 1);
            } else {
                cg::coalesced_group grp = cg::coalesced_threads();
                int base;
                if (grp.thread_rank() == 0) base = atomicAdd(ctr, (int)grp.size());
                base = grp.shfl(base, 0);
                __stcg(&uout[base + grp.thread_rank()], v);
            }
        }
        xsync(bar, GB, epoch);
        int newUsz = __ldcg(&g_szHist[g][t + 1]);
        t += 1;
        int visNow = n - newUsz;
        bool stuck = (visNow == vis);
        usz = newUsz;
        if (stuck) {
            // seed unreached node with min perm (scan new unvisited list)
            unsigned long long key = ~0ull;
            {
                const int* ulist = g_front[g][t & 1];
                for (int idx = gtid; idx < newUsz; idx += gsz) {
                    int v = __ldcg(&ulist[idx]);
                    key = ullmin2(key, ((unsigned long long)(unsigned)__ldg(&perm[v]) << 32) | (unsigned)v);
                }
            }
#pragma unroll
            for (int off = 16; off; off >>= 1)
                key = ullmin2(key, __shfl_down_sync(0xffffffffu, key, off));
            int wid = threadIdx.x >> 5;
            if (lane == 0) sK[wid] = key;
            __syncthreads();
            if (threadIdx.x < 32) {
                unsigned long long kk2 = sK[threadIdx.x];
#pragma unroll
                for (int off = 16; off; off >>= 1)
                    kk2 = ullmin2(kk2, __shfl_down_sync(0xffffffffu, kk2, off));
                if (threadIdx.x == 0 && kk2 != ~0ull) atomicMin(&g_seedkeyG[g], kk2);
            }
            xsync(bar, GB, epoch);
            if (gtid == 0) {
                unsigned long long kv = g_seedkeyG[g];
                if (kv != ~0ull) {
                    int idx = (int)(unsigned)(kv & 0xffffffffull);
                    __stcg(&hop[idx], t);
                }
                g_seedkeyG[g] = ~0ull;
            }
            xsync(bar, GB, epoch);
            vis = visNow + 1;
        } else {
            vis = visNow;
        }
    }

    // histogram of clipped hops
    {
        __shared__ int sh[256];
        for (int j = threadIdx.x; j < 256; j += 1024) sh[j] = 0;
        __syncthreads();
        for (int i = gtid; i < n; i += gsz) {
            int hv = min(__ldcg(&hop[i]), 15000);
            if (hv < 256) atomicAdd(&sh[hv], 1);
            else atomicAdd(&hist[hv], 1);
        }
        __syncthreads();
        for (int j = threadIdx.x; j < 256; j += 1024)
            if (sh[j]) atomicAdd(&hist[j], sh[j]);
    }
    xsync(bar, GB, epoch);

    // hstar: smallest hop whose cumulative count reaches k
    if (gb == 0) {
        __shared__ int sRun, sTot, sDone;
        if (threadIdx.x == 0) { sRun = 0; sDone = 0; }
        __syncthreads();
        for (int base = 0; base < HIST_BINS; base += 1024) {
            if (sDone) break;
            int h = base + threadIdx.x;
            int v = (h < HIST_BINS) ? __ldcg(&hist[h]) : 0;
            int incl = blockScanInc(v, sWarp);
            int P = sRun + incl;
            if (v > 0 && P >= k && P - v < k) { g_hstarG[g] = h; g_rremG[g] = k - (P - v); sDone = 1; }
            if (threadIdx.x == 1023) sTot = incl;
            __syncthreads();
            if (threadIdx.x == 0) sRun += sTot;
            __syncthreads();
        }
    }
    xsync(bar, GB, epoch);
    int hstar = *(volatile int*)&g_hstarG[g];
    int rrem = *(volatile int*)&g_rremG[g];

    // pstar: rrem-th smallest perm value among hop==hstar
    int chunk = (n + GB - 1) / GB;
    int v0 = gb * chunk, v1 = min(v0 + chunk, n);
    {
        int c = 0;
        for (int v = v0 + threadIdx.x; v < v1; v += 1024) {
            int j = __ldcg(&invp[v]);
            c += (min(__ldcg(&hop[j]), 15000) == hstar);
        }
#pragma unroll
        for (int off = 16; off; off >>= 1) c += __shfl_down_sync(0xffffffffu, c, off);
        int wid = threadIdx.x >> 5;
        if (lane == 0) sWarp[wid] = c;
        __syncthreads();
        if (threadIdx.x < 32) {
            int r = sWarp[threadIdx.x];
#pragma unroll
            for (int off = 16; off; off >>= 1) r += __shfl_down_sync(0xffffffffu, r, off);
            if (threadIdx.x == 0) g_blkCntG[g][gb] = r;
        }
    }
    xsync(bar, GB, epoch);
    if (gb == 0) {
        int b = threadIdx.x;
        int v = (b < GB) ? __ldcg(&g_blkCntG[g][b]) : 0;
        int incl = blockScanInc(v, sWarp);
        int excl = incl - v;
        if (b < GB && v > 0 && excl < rrem && rrem <= incl) {
            g_pselBlockG[g] = b; g_pselRemG[g] = rrem - excl;
        }
    }
    xsync(bar, GB, epoch);
    if (gb == *(volatile int*)&g_pselBlockG[g]) {
        int rem = *(volatile int*)&g_pselRemG[g];
        __shared__ int sRun2, sTot2, sDone2;
        if (threadIdx.x == 0) { sRun2 = 0; sDone2 = 0; }
        __syncthreads();
        for (int base = v0; base < v1; base += 1024) {
            if (sDone2) break;
            int v = base + threadIdx.x;
            int pred = 0;
            if (v < v1) {
                int j = __ldcg(&invp[v]);
                pred = (min(__ldcg(&hop[j]), 15000) == hstar);
            }
            int incl = blockScanInc(pred, sWarp);
            int cum = sRun2 + incl;
            if (pred && cum == rem) { g_pstarG[g] = v; sDone2 = 1; }
            if (threadIdx.x == 1023) sTot2 = incl;
            __syncthreads();
            if (threadIdx.x == 0) sRun2 += sTot2;
            __syncthreads();
        }
    }
    xsync(bar, GB, epoch);
    int pstar = *(volatile int*)&g_pstarG[g];
    for (int i = gtid; i < n; i += gsz) {
        int hv = min(__ldcg(&hop[i]), 15000);
        keep[i] = (hv < hstar) || (hv == hstar && __ldg(&perm[i]) <= pstar);
    }
    xexit(bar, GB, epoch);
}

// ============================================================================
// Kernel 3: annotate (warp per node): keep bits into colD + counts/inverses.
// ============================================================================

__global__ __launch_bounds__(256)
void annotate_kernel(int n) {
    int lane = threadIdx.x & 31;
    int warpId = (blockIdx.x * 256 + threadIdx.x) >> 5;
    int nW = gridDim.x * 8;
    for (int node = warpId; node < n; node += nW) {
        int s0 = g_rowD[node], s1 = g_rowD[node + 1];
        int c1 = 0, c2 = 0;
        for (int e = s0 + lane; e < s1; e += 32) {
            unsigned c = g_colD[e] & 0x3FFFFFFFu;
            unsigned k1 = (unsigned)__ldg(&g_keep1[c]);
            unsigned k2 = (unsigned)__ldg(&g_keep2[c]);
            g_colD[e] = c | (k1 << 30) | (k2 << 31);
            c1 += (int)k1; c2 += (int)k2;
        }
#pragma unroll
        for (int off = 16; off; off >>= 1) {
            c1 += __shfl_down_sync(0xffffffffu, c1, off);
            c2 += __shfl_down_sync(0xffffffffu, c2, off);
        }
        if (lane == 0) {
            g_inv1[node] = 1.f / (float)max(c1, 1);
            g_inv2[node] = 1.f / (float)max(c2, 1);
            g_invd[node] = 1.f / (float)max(s1 - s0, 1);
        }
    }
}

// ============================================================================
// Kernel 4: mega GCN — fp16 aggregation of 4 streams (HADD2/HFMA2), f32x2
// GEMV 2 nodes/warp, static smem; LAST block computes v.
// ============================================================================

#define MEGA_EDGE(cc)                                                          \
    do {                                                                       \
        unsigned s_ = (cc) & 0x3FFFFFFFu;                                      \
        __half2 f_ = FP[(size_t)s_ * 32 + lane];                               \
        __half2 g_ = FN[(size_t)s_ * 32 + lane];                               \
        aP = __hadd2(aP, f_);                                                  \
        aN = __hadd2(aN, g_);                                                  \
        unsigned b1_ = (unsigned)(((int)((cc) << 1)) >> 31) & 0x3C003C00u;     \
        unsigned b2_ = (unsigned)(((int)(cc)) >> 31) & 0x3C003C00u;            \
        aM1 = __hfma2(f_, u2h2(b1_), aM1);                                     \
        aM2 = __hfma2(f_, u2h2(b2_), aM2);                                     \
    } while (0)

__global__ __launch_bounds__(256)
void mega_gcn_kernel(const float* __restrict__ Wenc, const float* __restrict__ Wdisc,
                     int n, int k) {
    __shared__ float sW[4096];
    __shared__ __align__(8) float sxp[8][64][2];
    __shared__ __align__(8) float sxn[8][64][2];
    __shared__ __align__(8) float sx1[8][64][2];
    __shared__ __align__(8) float sx2[8][64][2];
    __shared__ double sSum[128];
    __shared__ int sLast;
    int tid = threadIdx.x;
    for (int j = tid; j < 4096; j += 256) sW[j] = Wenc[j];
    if (tid < 128) sSum[tid] = 0.0;
    __syncthreads();
    int warp = tid >> 5, lane = tid & 31;
    double A10 = 0.0, A11 = 0.0, A20 = 0.0, A21 = 0.0;
    const __half2* FP = reinterpret_cast<const __half2*>(g_feat16);
    const __half2* FN = reinterpret_cast<const __half2*>(g_featneg16);

    for (int nb = (blockIdx.x * 8 + warp) * 2; nb < n; nb += gridDim.x * 16) {
        int k1d[2], k2d[2];
#pragma unroll
        for (int j = 0; j < 2; j++) {
            int node = nb + j;
            bool valid = node < n;
            k1d[j] = valid ? (int)g_keep1[node] : 0;
            k2d[j] = valid ? (int)g_keep2[node] : 0;
            int s0 = valid ? g_rowD[node] : 0;
            int s1 = valid ? g_rowD[node + 1] : 0;

            __half2 aP = u2h2(0), aN = u2h2(0), aM1 = u2h2(0), aM2 = u2h2(0);

            int e2 = s0;
            while (e2 < s1 && (e2 & 3)) { MEGA_EDGE(__ldcs(&g_colD[e2])); e2++; }
            for (; e2 + 4 <= s1; e2 += 4) {
                uint4 c4 = *reinterpret_cast<const uint4*>(&g_colD[e2]);
                MEGA_EDGE(c4.x); MEGA_EDGE(c4.y); MEGA_EDGE(c4.z); MEGA_EDGE(c4.w);
            }
            while (e2 < s1) { MEGA_EDGE(__ldcs(&g_colD[e2])); e2++; }

            float invd = valid ? __ldg(&g_invd[node]) : 1.f;
            float i1 = valid ? __ldg(&g_inv1[node]) : 1.f;
            float i2 = valid ? __ldg(&g_inv2[node]) : 1.f;
            float2 P = __half22float2(aP), Q = __half22float2(aN);
            float2 M1 = __half22float2(aM1), M2 = __half22float2(aM2);
            sxp[warp][2 * lane][j] = P.x * invd; sxp[warp][2 * lane + 1][j] = P.y * invd;
            sxn[warp][2 * lane][j] = Q.x * invd; sxn[warp][2 * lane + 1][j] = Q.y * invd;
            sx1[warp][2 * lane][j] = M1.x * i1;  sx1[warp][2 * lane + 1][j] = M1.y * i1;
            sx2[warp][2 * lane][j] = M2.x * i2;  sx2[warp][2 * lane + 1][j] = M2.y * i2;
        }
        __syncwarp();

        // f32x2 packed GEMV: each ull accumulator = (node0, node1)
        ull oPa = 0, oPb = 0, oNa = 0, oNb = 0;
        ull o1a = 0, o1b = 0, o2a = 0, o2b = 0;
#pragma unroll 16
        for (int kk = 0; kk < 64; kk++) {
            float2 w = *reinterpret_cast<const float2*>(&sW[kk * 64 + 2 * lane]);
            ull wa = pack2(w.x, w.x);
            ull wb = pack2(w.y, w.y);
            ull xp = *reinterpret_cast<const ull*>(&sxp[warp][kk][0]);
            ull xn = *reinterpret_cast<const ull*>(&sxn[warp][kk][0]);
            ull x1 = *reinterpret_cast<const ull*>(&sx1[warp][kk][0]);
            ull x2 = *reinterpret_cast<const ull*>(&sx2[warp][kk][0]);
            oPa = fma2(xp, wa, oPa); oPb = fma2(xp, wb, oPb);
            oNa = fma2(xn, wa, oNa); oNb = fma2(xn, wb, oNb);
            o1a = fma2(x1, wa, o1a); o1b = fma2(x1, wb, o1b);
            o2a = fma2(x2, wa, o2a); o2b = fma2(x2, wb, o2b);
        }
        float opa[2], opb[2], ona[2], onb[2], m1a[2], m1b[2], m2a[2], m2b[2];
        unpack2(oPa, opa[0], opa[1]); unpack2(oPb, opb[0], opb[1]);
        unpack2(oNa, ona[0], ona[1]); unpack2(oNb, onb[0], onb[1]);
        unpack2(o1a, m1a[0], m1a[1]); unpack2(o1b, m1b[0], m1b[1]);
        unpack2(o2a, m2a[0], m2a[1]); unpack2(o2b, m2b[0], m2b[1]);
#pragma unroll
        for (int j = 0; j < 2; j++) {
            int node = nb + j;
            if (node < n) {
                reinterpret_cast<__half2*>(g_hpos16)[(size_t)node * 32 + lane] =
                    __floats2half2_rn(fmaxf(opa[j], 0.f), fmaxf(opb[j], 0.f));
                reinterpret_cast<__half2*>(g_hneg16)[(size_t)node * 32 + lane] =
                    __floats2half2_rn(fmaxf(ona[j], 0.f), fmaxf(onb[j], 0.f));
                if (k1d[j]) { A10 += (double)fmaxf(m1a[j], 0.f); A11 += (double)fmaxf(m1b[j], 0.f); }
                if (k2d[j]) { A20 += (double)fmaxf(m2a[j], 0.f); A21 += (double)fmaxf(m2b[j], 0.f); }
            }
        }
        __syncwarp();
    }
    atomicAdd(&sSum[2 * lane], A10);
    atomicAdd(&sSum[2 * lane + 1], A11);
    atomicAdd(&sSum[64 + 2 * lane], A20);
    atomicAdd(&sSum[64 + 2 * lane + 1], A21);
    __syncthreads();
    if (tid < 128) {
        double v = sSum[tid];
        if (v != 0.0) atomicAdd(&g_summary[tid], v);
    }

    if (tid == 0) {
        __threadfence();
        sLast = (atomicAdd(&g_ctrMega, 1u) == gridDim.x - 1);
    }
    __syncthreads();
    if (sLast) {
        __shared__ float ss[2][64];
        if (tid < 128) {
            double s = g_summary[tid] / (double)k;
            ss[tid >> 6][tid & 63] = (float)(1.0 / (1.0 + exp(-s)));
        }
        __syncthreads();
        if (tid < 128) {
            int p = tid >> 6, c = tid & 63;
            float v = 0.f;
#pragma unroll
            for (int b = 0; b < 64; b++) v += Wdisc[c * 64 + b] * ss[p][b];
            g_v[p][c] = v;
        }
        if (tid == 0) g_ctrMega = 0;
    }
}

// ============================================================================
// Kernel 5: BCE losses (streams fp16 h); last block writes final output.
// ============================================================================

__global__ __launch_bounds__(256)
void loss_kernel(float* __restrict__ out, int n) {
    __shared__ float sv0[64], sv1[64];
    __shared__ double sL[4];
    __shared__ int sLast;
    int tid = threadIdx.x;
    if (tid < 64) { sv0[tid] = g_v[0][tid]; sv1[tid] = g_v[1][tid]; }
    if (tid < 4) sL[tid] = 0.0;
    __syncthreads();
    int warp = tid >> 5, lane = tid & 31;
    float v00 = sv0[2 * lane], v01 = sv0[2 * lane + 1];
    float v10 = sv1[2 * lane], v11 = sv1[2 * lane + 1];
    double l0 = 0, l1 = 0, l2 = 0, l3 = 0;
    const __half2* HP = reinterpret_cast<const __half2*>(g_hpos16);
    const __half2* HN = reinterpret_cast<const __half2*>(g_hneg16);
    for (int node = blockIdx.x * 8 + warp; node < n; node += gridDim.x * 8) {
        float2 hp = __half22float2(HP[(size_t)node * 32 + lane]);
        float2 hn = __half22float2(HN[(size_t)node * 32 + lane]);
        float p1 = hp.x * v00 + hp.y * v01;
        float p2 = hp.x * v10 + hp.y * v11;
        float q1 = hn.x * v00 + hn.y * v01;
        float q2 = hn.x * v10 + hn.y * v11;
#pragma unroll
        for (int off = 16; off; off >>= 1) {
            p1 += __shfl_down_sync(0xffffffffu, p1, off);
            p2 += __shfl_down_sync(0xffffffffu, p2, off);
            q1 += __shfl_down_sync(0xffffffffu, q1, off);
            q2 += __shfl_down_sync(0xffffffffu, q2, off);
        }
        if (lane == 0) {
            l0 += (double)softplusf(-p1);
            l1 += (double)softplusf(q1);
            l2 += (double)softplusf(-p2);
            l3 += (double)softplusf(q2);
        }
    }
    if (lane == 0) {
        atomicAdd(&sL[0], l0); atomicAdd(&sL[1], l1);
        atomicAdd(&sL[2], l2); atomicAdd(&sL[3], l3);
    }
    __syncthreads();
    if (tid < 4) atomicAdd(&g_loss[tid], sL[tid]);

    if (tid == 0) {
        __threadfence();
        sLast = (atomicAdd(&g_ctrLoss, 1u) == gridDim.x - 1);
    }
    __syncthreads();
    if (sLast && tid == 0) {
        out[0] = (float)((g_loss[0] + g_loss[1] + g_loss[2] + g_loss[3]) / (double)n);
        g_ctrLoss = 0;
    }
}

// ============================================================================
// launch
// ============================================================================

extern "C" void kernel_launch(void* const* d_in, const int* in_sizes, int n_in,
                              void* d_out, int out_size) {
    const float* feat = (const float*)d_in[0];
    const float* Wenc = (const float*)d_in[1];
    const float* Wdisc = (const float*)d_in[2];
    const int* src = (const int*)d_in[3];
    const int* dst = (const int*)d_in[4];
    const int* permneg = (const int*)d_in[5];
    const int* perm1 = (const int*)d_in[6];
    const int* perm2 = (const int*)d_in[7];

    int e = in_sizes[3];
    int n = in_sizes[5];
    int k = (int)((double)n * 0.8);

    csr_kernel<<<CSRB, 1024>>>(feat, src, dst, permneg, e, n);
    bfs_dual_kernel<<<BFSB, 1024>>>(perm1, perm2, n, k);

    int aGrid = (n + 7) / 8;
    if (aGrid > 1480) aGrid = 1480;
    annotate_kernel<<<aGrid, 256>>>(n);

    int mGrid = (n + 15) / 16;
    if (mGrid > 1480) mGrid = 1480;
    mega_gcn_kernel<<<mGrid, 256>>>(Wenc, Wdisc, n, k);

    int lGrid = (n + 7) / 8;
    if (lGrid > 1480) lGrid = 1480;
    loss_kernel<<<lGrid, 256>>>((float*)d_out, n);
}

// round 16
// speedup vs baseline: 1.3396x; 1.0838x over previous
#include <cuda_runtime.h>
#include <cuda_fp16.h>
#include <cooperative_groups.h>
#include <math.h>

namespace cg = cooperative_groups;

// ============================================================================
// DGISubgraphCL — 5-launch pipeline:
//   csr (dst-CSR + fp16 feat + permuted neg feat) ->
//   bfs_dual (PULL BFS with rotating frontier BITMAPS + exact top-k) ->
//   annotate (warp/node: keep bits into colD + inv degrees) ->
//   mega GCN (4 streams, fp16 aggregation, f32x2 GEMV 2 nodes/warp;
//   last block computes v) -> loss (fp16 h; last block finalizes).
// ============================================================================

#define N_MAX 131072
#define E_MAX (N_MAX * 17)
#define HIST_BINS 15001
#define CSRB 264
#define BFSB 132
#define GB 66
#define MAX_SWEEPS 250
#define BMPW 4096   // N_MAX / 32 bitmap words

typedef unsigned long long ull;

// ---- device scratch ----
__device__ int g_rowD[N_MAX + 1], g_cntD[N_MAX], g_curD[N_MAX];
__device__ unsigned g_colD[E_MAX];          // after annotate: s | k1<<30 | k2<<31
__device__ __half g_feat16[(size_t)N_MAX * 64];
__device__ __half g_featneg16[(size_t)N_MAX * 64];
__device__ float g_inv1[N_MAX], g_inv2[N_MAX], g_invd[N_MAX];
__device__ int g_hopG[2][N_MAX];
__device__ int g_front[2][2][N_MAX];        // unvisited lists (double buffered)
__device__ unsigned g_bmp[2][3][BMPW];      // frontier bitmaps (3-way rotation)
__device__ int g_invpermG[2][N_MAX];
__device__ int g_histG[2][HIST_BINS];
__device__ int g_szHist[2][MAX_SWEEPS + 8];
__device__ unsigned char g_keep1[N_MAX];
__device__ unsigned char g_keep2[N_MAX];
__device__ __half g_hpos16[(size_t)N_MAX * 64];
__device__ __half g_hneg16[(size_t)N_MAX * 64];
__device__ double g_summary[128];
__device__ float g_v[2][64];
__device__ double g_loss[4];

__device__ int g_bsD[CSRB], g_offD[CSRB];
__device__ int g_blkCntG[2][GB];
__device__ unsigned long long g_seedkeyG[2];
__device__ int g_hstarG[2], g_rremG[2], g_pstarG[2], g_pselBlockG[2], g_pselRemG[2];

__device__ unsigned g_barC = 0;
__device__ unsigned g_barG[2] = {0, 0};
__device__ unsigned g_ctrMega = 0;
__device__ unsigned g_ctrLoss = 0;

// ============================================================================
// helpers
// ============================================================================

__device__ __forceinline__ ull pack2(float x, float y) {
    ull r; asm("mov.b64 %0, {%1, %2};" : "=l"(r) : "f"(x), "f"(y)); return r;
}
__device__ __forceinline__ void unpack2(ull v, float& x, float& y) {
    asm("mov.b64 {%0, %1}, %2;" : "=f"(x), "=f"(y) : "l"(v));
}
__device__ __forceinline__ ull fma2(ull a, ull b, ull c) {
    ull d; asm("fma.rn.f32x2 %0, %1, %2, %3;" : "=l"(d) : "l"(a), "l"(b), "l"(c)); return d;
}
__device__ __forceinline__ __half2 u2h2(unsigned u) {
    __half2 h; *reinterpret_cast<unsigned*>(&h) = u; return h;
}

__device__ __forceinline__ void xsync(unsigned* ctr, unsigned nblk, unsigned& epoch) {
    __syncthreads();
    if (threadIdx.x == 0) {
        __threadfence();
        unsigned target = (epoch + 1) * nblk;
        atomicAdd(ctr, 1u);
        while (*((volatile unsigned*)ctr) < target) {}
        __threadfence();   // gpu-scope: emits CCTL.IVALL -> L1D fresh after barrier
    }
    epoch++;
    __syncthreads();
}

__device__ __forceinline__ void xexit(unsigned* ctr, unsigned nblk, unsigned epoch) {
    __syncthreads();
    if (threadIdx.x == 0) {
        __threadfence();
        unsigned target = (epoch + 1) * nblk;
        if (atomicAdd(ctr, 1u) + 1 == target) *ctr = 0;
    }
}

__device__ __forceinline__ float softplusf(float x) {
    return fmaxf(x, 0.f) + log1pf(expf(-fabsf(x)));
}

__device__ __forceinline__ unsigned long long ullmin2(unsigned long long a, unsigned long long b) {
    return a < b ? a : b;
}

__device__ __forceinline__ int blockScanInc(int v, int* sWarp) {
    int lane = threadIdx.x & 31;
    int wid = threadIdx.x >> 5;
#pragma unroll
    for (int off = 1; off < 32; off <<= 1) {
        int t = __shfl_up_sync(0xffffffffu, v, off);
        if (lane >= off) v += t;
    }
    if (lane == 31) sWarp[wid] = v;
    __syncthreads();
    if (wid == 0) {
        int w = sWarp[lane];
#pragma unroll
        for (int off = 1; off < 32; off <<= 1) {
            int t = __shfl_up_sync(0xffffffffu, w, off);
            if (lane >= off) w += t;
        }
        sWarp[lane] = w;
    }
    __syncthreads();
    return v + (wid ? sWarp[wid - 1] : 0);
}

// ============================================================================
// Kernel 1: dst-CSR build + feat->fp16 (+ permuted neg table) + zeroing
// ============================================================================

__global__ __launch_bounds__(1024, 2)
void csr_kernel(const float* __restrict__ feat, const int* __restrict__ src,
                const int* __restrict__ dst, const int* __restrict__ permneg,
                int e, int n) {
    unsigned epoch = 0;
    int gtid = blockIdx.x * 1024 + threadIdx.x;
    int gsz = gridDim.x * 1024;

    for (int i = gtid; i < n; i += gsz) g_cntD[i] = 0;
    if (gtid < 4) g_loss[gtid] = 0.0;
    if (gtid < 128) g_summary[gtid] = 0.0;
    if (gtid == 0) g_rowD[n] = e;
    {
        int tot = n * 32;
        const float2* f2 = reinterpret_cast<const float2*>(feat);
        __half2* h2 = reinterpret_cast<__half2*>(g_feat16);
        for (int i = gtid; i < tot; i += gsz) h2[i] = __float22half2_rn(f2[i]);
    }
    xsync(&g_barC, gridDim.x, epoch);

    for (int i = gtid; i < e; i += gsz) atomicAdd(&g_cntD[dst[i]], 1);
    {
        int warp = gtid >> 5, lane = gtid & 31, nw = gsz >> 5;
        const __half2* fsrc = reinterpret_cast<const __half2*>(g_feat16);
        __half2* fdst = reinterpret_cast<__half2*>(g_featneg16);
        for (int i = warp; i < n; i += nw) {
            int r = __ldg(&permneg[i]);
            fdst[(size_t)i * 32 + lane] = fsrc[(size_t)r * 32 + lane];
        }
    }
    xsync(&g_barC, gridDim.x, epoch);

    __shared__ int sWarp[32];
    __shared__ int sRun, sTot;
    int chunk = (n + gridDim.x - 1) / gridDim.x;
    int b0 = blockIdx.x * chunk;
    int b1 = min(b0 + chunk, n);
    if (threadIdx.x == 0) sRun = 0;
    __syncthreads();
    for (int base = b0; base < b1; base += 1024) {
        int i = base + threadIdx.x;
        int v = (i < b1) ? __ldcg(&g_cntD[i]) : 0;
        int incl = blockScanInc(v, sWarp);
        if (i < b1) g_rowD[i] = sRun + incl - v;
        if (threadIdx.x == 1023) sTot = incl;
        __syncthreads();
        if (threadIdx.x == 0) sRun += sTot;
        __syncthreads();
    }
    if (threadIdx.x == 0) g_bsD[blockIdx.x] = sRun;
    xsync(&g_barC, gridDim.x, epoch);

    if (blockIdx.x == 0) {
        int b = threadIdx.x;
        int vD = (b < (int)gridDim.x) ? __ldcg(&g_bsD[b]) : 0;
        int incl = blockScanInc(vD, sWarp);
        if (b < (int)gridDim.x) g_offD[b] = incl - vD;
    }
    xsync(&g_barC, gridDim.x, epoch);

    {
        int oD = __ldcg(&g_offD[blockIdx.x]);
        for (int i = b0 + threadIdx.x; i < b1; i += 1024) {
            int vD = __ldcg(&g_rowD[i]) + oD;
            g_rowD[i] = vD; g_curD[i] = vD;
        }
    }
    xsync(&g_barC, gridDim.x, epoch);

    for (int i = gtid; i < e; i += gsz) {
        int d = dst[i];
        int pd = atomicAdd(&g_curD[d], 1);
        g_colD[pd] = (unsigned)src[i];
    }
    xexit(&g_barC, gridDim.x, epoch);
}

// ============================================================================
// Kernel 2: dual PULL BFS with rotating frontier bitmaps + exact top-k
// ============================================================================

__global__ __launch_bounds__(1024, 1)
void bfs_dual_kernel(const int* __restrict__ perm1, const int* __restrict__ perm2, int n, int k) {
    int g = (blockIdx.x < GB) ? 0 : 1;
    int gb = blockIdx.x - g * GB;
    const int* perm = g ? perm2 : perm1;
    unsigned char* keep = g ? g_keep2 : g_keep1;
    int* hop = g_hopG[g];
    int* invp = g_invpermG[g];
    int* hist = g_histG[g];
    unsigned* bar = &g_barG[g];
    unsigned epoch = 0;
    int gtid = gb * 1024 + threadIdx.x;
    int gsz = GB * 1024;
    const int INF = n;

    __shared__ int sWarp[32];
    __shared__ unsigned long long sK[32];

    int root = __ldg(&perm[0]);
    for (int i = gtid; i < n; i += gsz) {
        __stcg(&hop[i], (i == root) ? 0 : INF);
        __stcg(&invp[__ldg(&perm[i])], i);
        if (i != root) __stcg(&g_front[g][0][i - (i > root)], i);
    }
    {
        unsigned* B = &g_bmp[g][0][0];   // linear over [3][BMPW]
        int rw = root >> 5;
        for (int i = gtid; i < 3 * BMPW; i += gsz)
            __stcg(&B[i], (i == rw) ? (1u << (root & 31)) : 0u);
    }
    for (int i = gtid; i < HIST_BINS; i += gsz) __stcg(&hist[i], 0);
    for (int i = gtid; i < MAX_SWEEPS + 8; i += gsz) __stcg(&g_szHist[g][i], 0);
    if (gtid == 0) {
        __stcg(&g_szHist[g][0], n - 1);
        g_seedkeyG[g] = ~0ull;
    }
    xsync(bar, GB, epoch);

    // ---- pull BFS over the unvisited list, bitmap frontier probes ----
    // bitmap[t%3] == {v : hop[v]==t}; sweep t reads it, writes (t+1)%3,
    // clears (t+2)%3 (read two sweeps ago, race-free). Exact replica of the
    // reference synchronous min-relaxation; seeds OR into the just-written map.
    int vis = 1;
    int usz = n - 1;
    int t = 0;
    int lane = threadIdx.x & 31;
    while (vis <= k && t < MAX_SWEEPS) {
        const int* uin = g_front[g][t & 1];
        int* uout = g_front[g][(t + 1) & 1];
        int* ctr = &g_szHist[g][t + 1];
        const unsigned* bmpR = g_bmp[g][t % 3];
        unsigned* bmpW = g_bmp[g][(t + 1) % 3];
        unsigned* bmpC = g_bmp[g][(t + 2) % 3];
        for (int i = gtid; i < BMPW; i += gsz) __stcg(&bmpC[i], 0u);
        for (int idx = gtid; idx < usz; idx += gsz) {
            int v = __ldcg(&uin[idx]);
            if (__ldcg(&hop[v]) != INF) continue;   // seeded last round: drop
            int s0 = g_rowD[v], s1 = g_rowD[v + 1];
            bool found = false;
            int e2 = s0;
            for (; e2 + 4 <= s1; e2 += 4) {
                unsigned c0 = __ldg(&g_colD[e2]);
                unsigned c1 = __ldg(&g_colD[e2 + 1]);
                unsigned c2 = __ldg(&g_colD[e2 + 2]);
                unsigned c3 = __ldg(&g_colD[e2 + 3]);
                unsigned b = ((bmpR[c0 >> 5] >> (c0 & 31)) & 1u)
                           | ((bmpR[c1 >> 5] >> (c1 & 31)) & 1u)
                           | ((bmpR[c2 >> 5] >> (c2 & 31)) & 1u)
                           | ((bmpR[c3 >> 5] >> (c3 & 31)) & 1u);
                if (b) { found = true; break; }
            }
            if (!found) {
                for (; e2 < s1; e2++) {
                    unsigned c = __ldg(&g_colD[e2]);
                    if ((bmpR[c >> 5] >> (c & 31)) & 1u) { found = true; break; }
                }
            }
            if (found) {
                __stcg(&hop[v], t + 1);
                atomicOr(&bmpW[v >> 5], 1u << (v & 31));
            } else {
                cg::coalesced_group grp = cg::coalesced_threads();
                int base;
                if (grp.thread_rank() == 0) base = atomicAdd(ctr, (int)grp.size());
                base = grp.shfl(base, 0);
                __stcg(&uout[base + grp.thread_rank()], v);
            }
        }
        xsync(bar, GB, epoch);
        int newUsz = __ldcg(&g_szHist[g][t + 1]);
        t += 1;
        int visNow = n - newUsz;
        bool stuck = (visNow == vis);
        usz = newUsz;
        if (stuck) {
            unsigned long long key = ~0ull;
            {
                const int* ulist = g_front[g][t & 1];
                for (int idx = gtid; idx < newUsz; idx += gsz) {
                    int v = __ldcg(&ulist[idx]);
                    key = ullmin2(key, ((unsigned long long)(unsigned)__ldg(&perm[v]) << 32) | (unsigned)v);
                }
            }
#pragma unroll
            for (int off = 16; off; off >>= 1)
                key = ullmin2(key, __shfl_down_sync(0xffffffffu, key, off));
            int wid = threadIdx.x >> 5;
            if (lane == 0) sK[wid] = key;
            __syncthreads();
            if (threadIdx.x < 32) {
                unsigned long long kk2 = sK[threadIdx.x];
#pragma unroll
                for (int off = 16; off; off >>= 1)
                    kk2 = ullmin2(kk2, __shfl_down_sync(0xffffffffu, kk2, off));
                if (threadIdx.x == 0 && kk2 != ~0ull) atomicMin(&g_seedkeyG[g], kk2);
            }
            xsync(bar, GB, epoch);
            if (gtid == 0) {
                unsigned long long kv = g_seedkeyG[g];
                if (kv != ~0ull) {
                    int idx = (int)(unsigned)(kv & 0xffffffffull);
                    __stcg(&hop[idx], t);
                    atomicOr(&g_bmp[g][t % 3][idx >> 5], 1u << (idx & 31));
                }
                g_seedkeyG[g] = ~0ull;
            }
            xsync(bar, GB, epoch);
            vis = visNow + 1;
        } else {
            vis = visNow;
        }
    }

    // histogram of clipped hops
    {
        __shared__ int sh[256];
        for (int j = threadIdx.x; j < 256; j += 1024) sh[j] = 0;
        __syncthreads();
        for (int i = gtid; i < n; i += gsz) {
            int hv = min(__ldcg(&hop[i]), 15000);
            if (hv < 256) atomicAdd(&sh[hv], 1);
            else atomicAdd(&hist[hv], 1);
        }
        __syncthreads();
        for (int j = threadIdx.x; j < 256; j += 1024)
            if (sh[j]) atomicAdd(&hist[j], sh[j]);
    }
    xsync(bar, GB, epoch);

    // hstar
    if (gb == 0) {
        __shared__ int sRun, sTot, sDone;
        if (threadIdx.x == 0) { sRun = 0; sDone = 0; }
        __syncthreads();
        for (int base = 0; base < HIST_BINS; base += 1024) {
            if (sDone) break;
            int h = base + threadIdx.x;
            int v = (h < HIST_BINS) ? __ldcg(&hist[h]) : 0;
            int incl = blockScanInc(v, sWarp);
            int P = sRun + incl;
            if (v > 0 && P >= k && P - v < k) { g_hstarG[g] = h; g_rremG[g] = k - (P - v); sDone = 1; }
            if (threadIdx.x == 1023) sTot = incl;
            __syncthreads();
            if (threadIdx.x == 0) sRun += sTot;
            __syncthreads();
        }
    }
    xsync(bar, GB, epoch);
    int hstar = *(volatile int*)&g_hstarG[g];
    int rrem = *(volatile int*)&g_rremG[g];

    // pstar
    int chunk = (n + GB - 1) / GB;
    int v0 = gb * chunk, v1 = min(v0 + chunk, n);
    {
        int c = 0;
        for (int v = v0 + threadIdx.x; v < v1; v += 1024) {
            int j = __ldcg(&invp[v]);
            c += (min(__ldcg(&hop[j]), 15000) == hstar);
        }
#pragma unroll
        for (int off = 16; off; off >>= 1) c += __shfl_down_sync(0xffffffffu, c, off);
        int wid = threadIdx.x >> 5;
        if (lane == 0) sWarp[wid] = c;
        __syncthreads();
        if (threadIdx.x < 32) {
            int r = sWarp[threadIdx.x];
#pragma unroll
            for (int off = 16; off; off >>= 1) r += __shfl_down_sync(0xffffffffu, r, off);
            if (threadIdx.x == 0) g_blkCntG[g][gb] = r;
        }
    }
    xsync(bar, GB, epoch);
    if (gb == 0) {
        int b = threadIdx.x;
        int v = (b < GB) ? __ldcg(&g_blkCntG[g][b]) : 0;
        int incl = blockScanInc(v, sWarp);
        int excl = incl - v;
        if (b < GB && v > 0 && excl < rrem && rrem <= incl) {
            g_pselBlockG[g] = b; g_pselRemG[g] = rrem - excl;
        }
    }
    xsync(bar, GB, epoch);
    if (gb == *(volatile int*)&g_pselBlockG[g]) {
        int rem = *(volatile int*)&g_pselRemG[g];
        __shared__ int sRun2, sTot2, sDone2;
        if (threadIdx.x == 0) { sRun2 = 0; sDone2 = 0; }
        __syncthreads();
        for (int base = v0; base < v1; base += 1024) {
            if (sDone2) break;
            int v = base + threadIdx.x;
            int pred = 0;
            if (v < v1) {
                int j = __ldcg(&invp[v]);
                pred = (min(__ldcg(&hop[j]), 15000) == hstar);
            }
            int incl = blockScanInc(pred, sWarp);
            int cum = sRun2 + incl;
            if (pred && cum == rem) { g_pstarG[g] = v; sDone2 = 1; }
            if (threadIdx.x == 1023) sTot2 = incl;
            __syncthreads();
            if (threadIdx.x == 0) sRun2 += sTot2;
            __syncthreads();
        }
    }
    xsync(bar, GB, epoch);
    int pstar = *(volatile int*)&g_pstarG[g];
    for (int i = gtid; i < n; i += gsz) {
        int hv = min(__ldcg(&hop[i]), 15000);
        keep[i] = (hv < hstar) || (hv == hstar && __ldg(&perm[i]) <= pstar);
    }
    xexit(bar, GB, epoch);
}

// ============================================================================
// Kernel 3: annotate (warp per node): keep bits into colD + counts/inverses.
// ============================================================================

__global__ __launch_bounds__(256)
void annotate_kernel(int n) {
    int lane = threadIdx.x & 31;
    int warpId = (blockIdx.x * 256 + threadIdx.x) >> 5;
    int nW = gridDim.x * 8;
    for (int node = warpId; node < n; node += nW) {
        int s0 = g_rowD[node], s1 = g_rowD[node + 1];
        int c1 = 0, c2 = 0;
        for (int e = s0 + lane; e < s1; e += 32) {
            unsigned c = g_colD[e] & 0x3FFFFFFFu;
            unsigned k1 = (unsigned)__ldg(&g_keep1[c]);
            unsigned k2 = (unsigned)__ldg(&g_keep2[c]);
            g_colD[e] = c | (k1 << 30) | (k2 << 31);
            c1 += (int)k1; c2 += (int)k2;
        }
#pragma unroll
        for (int off = 16; off; off >>= 1) {
            c1 += __shfl_down_sync(0xffffffffu, c1, off);
            c2 += __shfl_down_sync(0xffffffffu, c2, off);
        }
        if (lane == 0) {
            g_inv1[node] = 1.f / (float)max(c1, 1);
            g_inv2[node] = 1.f / (float)max(c2, 1);
            g_invd[node] = 1.f / (float)max(s1 - s0, 1);
        }
    }
}

// ============================================================================
// Kernel 4: mega GCN — fp16 aggregation of 4 streams (HADD2/HFMA2), f32x2
// GEMV 2 nodes/warp, static smem; LAST block computes v.
// ============================================================================

#define MEGA_EDGE(cc)                                                          \
    do {                                                                       \
        unsigned s_ = (cc) & 0x3FFFFFFFu;                                      \
        __half2 f_ = FP[(size_t)s_ * 32 + lane];                               \
        __half2 g_ = FN[(size_t)s_ * 32 + lane];                               \
        aP = __hadd2(aP, f_);                                                  \
        aN = __hadd2(aN, g_);                                                  \
        unsigned b1_ = (unsigned)(((int)((cc) << 1)) >> 31) & 0x3C003C00u;     \
        unsigned b2_ = (unsigned)(((int)(cc)) >> 31) & 0x3C003C00u;            \
        aM1 = __hfma2(f_, u2h2(b1_), aM1);                                     \
        aM2 = __hfma2(f_, u2h2(b2_), aM2);                                     \
    } while (0)

__global__ __launch_bounds__(256)
void mega_gcn_kernel(const float* __restrict__ Wenc, const float* __restrict__ Wdisc,
                     int n, int k) {
    __shared__ float sW[4096];
    __shared__ __align__(8) float sxp[8][64][2];
    __shared__ __align__(8) float sxn[8][64][2];
    __shared__ __align__(8) float sx1[8][64][2];
    __shared__ __align__(8) float sx2[8][64][2];
    __shared__ double sSum[128];
    __shared__ int sLast;
    int tid = threadIdx.x;
    for (int j = tid; j < 4096; j += 256) sW[j] = Wenc[j];
    if (tid < 128) sSum[tid] = 0.0;
    __syncthreads();
    int warp = tid >> 5, lane = tid & 31;
    double A10 = 0.0, A11 = 0.0, A20 = 0.0, A21 = 0.0;
    const __half2* FP = reinterpret_cast<const __half2*>(g_feat16);
    const __half2* FN = reinterpret_cast<const __half2*>(g_featneg16);

    for (int nb = (blockIdx.x * 8 + warp) * 2; nb < n; nb += gridDim.x * 16) {
        int k1d[2], k2d[2];
#pragma unroll
        for (int j = 0; j < 2; j++) {
            int node = nb + j;
            bool valid = node < n;
            k1d[j] = valid ? (int)g_keep1[node] : 0;
            k2d[j] = valid ? (int)g_keep2[node] : 0;
            int s0 = valid ? g_rowD[node] : 0;
            int s1 = valid ? g_rowD[node + 1] : 0;

            __half2 aP = u2h2(0), aN = u2h2(0), aM1 = u2h2(0), aM2 = u2h2(0);

            int e2 = s0;
            while (e2 < s1 && (e2 & 3)) { MEGA_EDGE(__ldcs(&g_colD[e2])); e2++; }
            for (; e2 + 4 <= s1; e2 += 4) {
                uint4 c4 = *reinterpret_cast<const uint4*>(&g_colD[e2]);
                MEGA_EDGE(c4.x); MEGA_EDGE(c4.y); MEGA_EDGE(c4.z); MEGA_EDGE(c4.w);
            }
            while (e2 < s1) { MEGA_EDGE(__ldcs(&g_colD[e2])); e2++; }

            float invd = valid ? __ldg(&g_invd[node]) : 1.f;
            float i1 = valid ? __ldg(&g_inv1[node]) : 1.f;
            float i2 = valid ? __ldg(&g_inv2[node]) : 1.f;
            float2 P = __half22float2(aP), Q = __half22float2(aN);
            float2 M1 = __half22float2(aM1), M2 = __half22float2(aM2);
            sxp[warp][2 * lane][j] = P.x * invd; sxp[warp][2 * lane + 1][j] = P.y * invd;
            sxn[warp][2 * lane][j] = Q.x * invd; sxn[warp][2 * lane + 1][j] = Q.y * invd;
            sx1[warp][2 * lane][j] = M1.x * i1;  sx1[warp][2 * lane + 1][j] = M1.y * i1;
            sx2[warp][2 * lane][j] = M2.x * i2;  sx2[warp][2 * lane + 1][j] = M2.y * i2;
        }
        __syncwarp();

        ull oPa = 0, oPb = 0, oNa = 0, oNb = 0;
        ull o1a = 0, o1b = 0, o2a = 0, o2b = 0;
#pragma unroll 16
        for (int kk = 0; kk < 64; kk++) {
            float2 w = *reinterpret_cast<const float2*>(&sW[kk * 64 + 2 * lane]);
            ull wa = pack2(w.x, w.x);
            ull wb = pack2(w.y, w.y);
            ull xp = *reinterpret_cast<const ull*>(&sxp[warp][kk][0]);
            ull xn = *reinterpret_cast<const ull*>(&sxn[warp][kk][0]);
            ull x1 = *reinterpret_cast<const ull*>(&sx1[warp][kk][0]);
            ull x2 = *reinterpret_cast<const ull*>(&sx2[warp][kk][0]);
            oPa = fma2(xp, wa, oPa); oPb = fma2(xp, wb, oPb);
            oNa = fma2(xn, wa, oNa); oNb = fma2(xn, wb, oNb);
            o1a = fma2(x1, wa, o1a); o1b = fma2(x1, wb, o1b);
            o2a = fma2(x2, wa, o2a); o2b = fma2(x2, wb, o2b);
        }
        float opa[2], opb[2], ona[2], onb[2], m1a[2], m1b[2], m2a[2], m2b[2];
        unpack2(oPa, opa[0], opa[1]); unpack2(oPb, opb[0], opb[1]);
        unpack2(oNa, ona[0], ona[1]); unpack2(oNb, onb[0], onb[1]);
        unpack2(o1a, m1a[0], m1a[1]); unpack2(o1b, m1b[0], m1b[1]);
        unpack2(o2a, m2a[0], m2a[1]); unpack2(o2b, m2b[0], m2b[1]);
#pragma unroll
        for (int j = 0; j < 2; j++) {
            int node = nb + j;
            if (node < n) {
                reinterpret_cast<__half2*>(g_hpos16)[(size_t)node * 32 + lane] =
                    __floats2half2_rn(fmaxf(opa[j], 0.f), fmaxf(opb[j], 0.f));
                reinterpret_cast<__half2*>(g_hneg16)[(size_t)node * 32 + lane] =
                    __floats2half2_rn(fmaxf(ona[j], 0.f), fmaxf(onb[j], 0.f));
                if (k1d[j]) { A10 += (double)fmaxf(m1a[j], 0.f); A11 += (double)fmaxf(m1b[j], 0.f); }
                if (k2d[j]) { A20 += (double)fmaxf(m2a[j], 0.f); A21 += (double)fmaxf(m2b[j], 0.f); }
            }
        }
        __syncwarp();
    }
    atomicAdd(&sSum[2 * lane], A10);
    atomicAdd(&sSum[2 * lane + 1], A11);
    atomicAdd(&sSum[64 + 2 * lane], A20);
    atomicAdd(&sSum[64 + 2 * lane + 1], A21);
    __syncthreads();
    if (tid < 128) {
        double v = sSum[tid];
        if (v != 0.0) atomicAdd(&g_summary[tid], v);
    }

    if (tid == 0) {
        __threadfence();
        sLast = (atomicAdd(&g_ctrMega, 1u) == gridDim.x - 1);
    }
    __syncthreads();
    if (sLast) {
        __shared__ float ss[2][64];
        if (tid < 128) {
            double s = g_summary[tid] / (double)k;
            ss[tid >> 6][tid & 63] = (float)(1.0 / (1.0 + exp(-s)));
        }
        __syncthreads();
        if (tid < 128) {
            int p = tid >> 6, c = tid & 63;
            float v = 0.f;
#pragma unroll
            for (int b = 0; b < 64; b++) v += Wdisc[c * 64 + b] * ss[p][b];
            g_v[p][c] = v;
        }
        if (tid == 0) g_ctrMega = 0;
    }
}

// ============================================================================
// Kernel 5: BCE losses (streams fp16 h); last block writes final output.
// ============================================================================

__global__ __launch_bounds__(256)
void loss_kernel(float* __restrict__ out, int n) {
    __shared__ float sv0[64], sv1[64];
    __shared__ double sL[4];
    __shared__ int sLast;
    int tid = threadIdx.x;
    if (tid < 64) { sv0[tid] = g_v[0][tid]; sv1[tid] = g_v[1][tid]; }
    if (tid < 4) sL[tid] = 0.0;
    __syncthreads();
    int warp = tid >> 5, lane = tid & 31;
    float v00 = sv0[2 * lane], v01 = sv0[2 * lane + 1];
    float v10 = sv1[2 * lane], v11 = sv1[2 * lane + 1];
    double l0 = 0, l1 = 0, l2 = 0, l3 = 0;
    const __half2* HP = reinterpret_cast<const __half2*>(g_hpos16);
    const __half2* HN = reinterpret_cast<const __half2*>(g_hneg16);
    for (int node = blockIdx.x * 8 + warp; node < n; node += gridDim.x * 8) {
        float2 hp = __half22float2(HP[(size_t)node * 32 + lane]);
        float2 hn = __half22float2(HN[(size_t)node * 32 + lane]);
        float p1 = hp.x * v00 + hp.y * v01;
        float p2 = hp.x * v10 + hp.y * v11;
        float q1 = hn.x * v00 + hn.y * v01;
        float q2 = hn.x * v10 + hn.y * v11;
#pragma unroll
        for (int off = 16; off; off >>= 1) {
            p1 += __shfl_down_sync(0xffffffffu, p1, off);
            p2 += __shfl_down_sync(0xffffffffu, p2, off);
            q1 += __shfl_down_sync(0xffffffffu, q1, off);
            q2 += __shfl_down_sync(0xffffffffu, q2, off);
        }
        if (lane == 0) {
            l0 += (double)softplusf(-p1);
            l1 += (double)softplusf(q1);
            l2 += (double)softplusf(-p2);
            l3 += (double)softplusf(q2);
        }
    }
    if (lane == 0) {
        atomicAdd(&sL[0], l0); atomicAdd(&sL[1], l1);
        atomicAdd(&sL[2], l2); atomicAdd(&sL[3], l3);
    }
    __syncthreads();
    if (tid < 4) atomicAdd(&g_loss[tid], sL[tid]);

    if (tid == 0) {
        __threadfence();
        sLast = (atomicAdd(&g_ctrLoss, 1u) == gridDim.x - 1);
    }
    __syncthreads();
    if (sLast && tid == 0) {
        out[0] = (float)((g_loss[0] + g_loss[1] + g_loss[2] + g_loss[3]) / (double)n);
        g_ctrLoss = 0;
    }
}

// ============================================================================
// launch
// ============================================================================

extern "C" void kernel_launch(void* const* d_in, const int* in_sizes, int n_in,
                              void* d_out, int out_size) {
    const float* feat = (const float*)d_in[0];
    const float* Wenc = (const float*)d_in[1];
    const float* Wdisc = (const float*)d_in[2];
    const int* src = (const int*)d_in[3];
    const int* dst = (const int*)d_in[4];
    const int* permneg = (const int*)d_in[5];
    const int* perm1 = (const int*)d_in[6];
    const int* perm2 = (const int*)d_in[7];

    int e = in_sizes[3];
    int n = in_sizes[5];
    int k = (int)((double)n * 0.8);

    csr_kernel<<<CSRB, 1024>>>(feat, src, dst, permneg, e, n);
    bfs_dual_kernel<<<BFSB, 1024>>>(perm1, perm2, n, k);

    int aGrid = (n + 7) / 8;
    if (aGrid > 1480) aGrid = 1480;
    annotate_kernel<<<aGrid, 256>>>(n);

    int mGrid = (n + 15) / 16;
    if (mGrid > 1480) mGrid = 1480;
    mega_gcn_kernel<<<mGrid, 256>>>(Wenc, Wdisc, n, k);

    int lGrid = (n + 7) / 8;
    if (lGrid > 1480) lGrid = 1480;
    loss_kernel<<<lGrid, 256>>>((float*)d_out, n);
}

// round 17
// speedup vs baseline: 1.3624x; 1.0170x over previous
#include <cuda_runtime.h>
#include <cuda_fp16.h>
#include <cooperative_groups.h>
#include <math.h>

namespace cg = cooperative_groups;

// ============================================================================
// DGISubgraphCL — 5-launch pipeline:
//   csr (dst-CSR + fp16 feat + INTERLEAVED pos/neg table) ->
//   bfs_dual (PULL BFS, rotating frontier bitmaps + exact top-k) ->
//   annotate (warp/node: keep bits into colD + inv degrees) ->
//   mega GCN (4 streams, fp16 aggregation w/ single 8B gather/edge,
//   f32x2 GEMV 2 nodes/warp; last block computes v) ->
//   loss (fp16 h, f32x2 packed 2-node reduction; last block finalizes).
// ============================================================================

#define N_MAX 131072
#define E_MAX (N_MAX * 17)
#define HIST_BINS 15001
#define CSRB 264
#define BFSB 132
#define GB 66
#define MAX_SWEEPS 250
#define BMPW 4096   // N_MAX / 32 bitmap words

typedef unsigned long long ull;

// ---- device scratch ----
__device__ int g_rowD[N_MAX + 1], g_cntD[N_MAX], g_curD[N_MAX];
__device__ unsigned g_colD[E_MAX];          // after annotate: s | k1<<30 | k2<<31
__device__ __half g_feat16[(size_t)N_MAX * 64];
__device__ ull g_featPN[(size_t)N_MAX * 32];   // lane-interleaved (fp half2 | fn half2<<32)
__device__ float g_inv1[N_MAX], g_inv2[N_MAX], g_invd[N_MAX];
__device__ int g_hopG[2][N_MAX];
__device__ int g_front[2][2][N_MAX];
__device__ unsigned g_bmp[2][3][BMPW];
__device__ int g_invpermG[2][N_MAX];
__device__ int g_histG[2][HIST_BINS];
__device__ int g_szHist[2][MAX_SWEEPS + 8];
__device__ unsigned char g_keep1[N_MAX];
__device__ unsigned char g_keep2[N_MAX];
__device__ __half g_hpos16[(size_t)N_MAX * 64];
__device__ __half g_hneg16[(size_t)N_MAX * 64];
__device__ double g_summary[128];
__device__ float g_v[2][64];
__device__ double g_loss[4];

__device__ int g_bsD[CSRB], g_offD[CSRB];
__device__ int g_blkCntG[2][GB];
__device__ unsigned long long g_seedkeyG[2];
__device__ int g_hstarG[2], g_rremG[2], g_pstarG[2], g_pselBlockG[2], g_pselRemG[2];

__device__ unsigned g_barC = 0;
__device__ unsigned g_barG[2] = {0, 0};
__device__ unsigned g_ctrMega = 0;
__device__ unsigned g_ctrLoss = 0;

// ============================================================================
// helpers
// ============================================================================

__device__ __forceinline__ ull pack2(float x, float y) {
    ull r; asm("mov.b64 %0, {%1, %2};" : "=l"(r) : "f"(x), "f"(y)); return r;
}
__device__ __forceinline__ void unpack2(ull v, float& x, float& y) {
    asm("mov.b64 {%0, %1}, %2;" : "=f"(x), "=f"(y) : "l"(v));
}
__device__ __forceinline__ ull fma2(ull a, ull b, ull c) {
    ull d; asm("fma.rn.f32x2 %0, %1, %2, %3;" : "=l"(d) : "l"(a), "l"(b), "l"(c)); return d;
}
__device__ __forceinline__ __half2 u2h2(unsigned u) {
    __half2 h; *reinterpret_cast<unsigned*>(&h) = u; return h;
}

__device__ __forceinline__ void xsync(unsigned* ctr, unsigned nblk, unsigned& epoch) {
    __syncthreads();
    if (threadIdx.x == 0) {
        __threadfence();
        unsigned target = (epoch + 1) * nblk;
        atomicAdd(ctr, 1u);
        while (*((volatile unsigned*)ctr) < target) {}
        __threadfence();
    }
    epoch++;
    __syncthreads();
}

__device__ __forceinline__ void xexit(unsigned* ctr, unsigned nblk, unsigned epoch) {
    __syncthreads();
    if (threadIdx.x == 0) {
        __threadfence();
        unsigned target = (epoch + 1) * nblk;
        if (atomicAdd(ctr, 1u) + 1 == target) *ctr = 0;
    }
}

__device__ __forceinline__ float softplusf(float x) {
    return fmaxf(x, 0.f) + log1pf(expf(-fabsf(x)));
}

__device__ __forceinline__ unsigned long long ullmin2(unsigned long long a, unsigned long long b) {
    return a < b ? a : b;
}

__device__ __forceinline__ int blockScanInc(int v, int* sWarp) {
    int lane = threadIdx.x & 31;
    int wid = threadIdx.x >> 5;
#pragma unroll
    for (int off = 1; off < 32; off <<= 1) {
        int t = __shfl_up_sync(0xffffffffu, v, off);
        if (lane >= off) v += t;
    }
    if (lane == 31) sWarp[wid] = v;
    __syncthreads();
    if (wid == 0) {
        int w = sWarp[lane];
#pragma unroll
        for (int off = 1; off < 32; off <<= 1) {
            int t = __shfl_up_sync(0xffffffffu, w, off);
            if (lane >= off) w += t;
        }
        sWarp[lane] = w;
    }
    __syncthreads();
    return v + (wid ? sWarp[wid - 1] : 0);
}

// ============================================================================
// Kernel 1: dst-CSR build + fp16 feat + interleaved PN table + zeroing
// ============================================================================

__global__ __launch_bounds__(1024, 2)
void csr_kernel(const float* __restrict__ feat, const int* __restrict__ src,
                const int* __restrict__ dst, const int* __restrict__ permneg,
                int e, int n) {
    unsigned epoch = 0;
    int gtid = blockIdx.x * 1024 + threadIdx.x;
    int gsz = gridDim.x * 1024;

    for (int i = gtid; i < n; i += gsz) g_cntD[i] = 0;
    if (gtid < 4) g_loss[gtid] = 0.0;
    if (gtid < 128) g_summary[gtid] = 0.0;
    if (gtid == 0) g_rowD[n] = e;
    {
        int tot = n * 32;
        const float2* f2 = reinterpret_cast<const float2*>(feat);
        __half2* h2 = reinterpret_cast<__half2*>(g_feat16);
        for (int i = gtid; i < tot; i += gsz) h2[i] = __float22half2_rn(f2[i]);
    }
    xsync(&g_barC, gridDim.x, epoch);

    // count in-degrees + build interleaved (fp, fn) table
    for (int i = gtid; i < e; i += gsz) atomicAdd(&g_cntD[dst[i]], 1);
    {
        int warp = gtid >> 5, lane = gtid & 31, nw = gsz >> 5;
        const unsigned* fsrc = reinterpret_cast<const unsigned*>(g_feat16);
        for (int i = warp; i < n; i += nw) {
            int r = __ldg(&permneg[i]);
            unsigned fp = fsrc[(size_t)i * 32 + lane];
            unsigned fn = fsrc[(size_t)r * 32 + lane];
            g_featPN[(size_t)i * 32 + lane] = ((ull)fn << 32) | (ull)fp;
        }
    }
    xsync(&g_barC, gridDim.x, epoch);

    __shared__ int sWarp[32];
    __shared__ int sRun, sTot;
    int chunk = (n + gridDim.x - 1) / gridDim.x;
    int b0 = blockIdx.x * chunk;
    int b1 = min(b0 + chunk, n);
    if (threadIdx.x == 0) sRun = 0;
    __syncthreads();
    for (int base = b0; base < b1; base += 1024) {
        int i = base + threadIdx.x;
        int v = (i < b1) ? __ldcg(&g_cntD[i]) : 0;
        int incl = blockScanInc(v, sWarp);
        if (i < b1) g_rowD[i] = sRun + incl - v;
        if (threadIdx.x == 1023) sTot = incl;
        __syncthreads();
        if (threadIdx.x == 0) sRun += sTot;
        __syncthreads();
    }
    if (threadIdx.x == 0) g_bsD[blockIdx.x] = sRun;
    xsync(&g_barC, gridDim.x, epoch);

    if (blockIdx.x == 0) {
        int b = threadIdx.x;
        int vD = (b < (int)gridDim.x) ? __ldcg(&g_bsD[b]) : 0;
        int incl = blockScanInc(vD, sWarp);
        if (b < (int)gridDim.x) g_offD[b] = incl - vD;
    }
    xsync(&g_barC, gridDim.x, epoch);

    {
        int oD = __ldcg(&g_offD[blockIdx.x]);
        for (int i = b0 + threadIdx.x; i < b1; i += 1024) {
            int vD = __ldcg(&g_rowD[i]) + oD;
            g_rowD[i] = vD; g_curD[i] = vD;
        }
    }
    xsync(&g_barC, gridDim.x, epoch);

    for (int i = gtid; i < e; i += gsz) {
        int d = dst[i];
        int pd = atomicAdd(&g_curD[d], 1);
        g_colD[pd] = (unsigned)src[i];
    }
    xexit(&g_barC, gridDim.x, epoch);
}

// ============================================================================
// Kernel 2: dual PULL BFS with rotating frontier bitmaps + exact top-k
// ============================================================================

__global__ __launch_bounds__(1024, 1)
void bfs_dual_kernel(const int* __restrict__ perm1, const int* __restrict__ perm2, int n, int k) {
    int g = (blockIdx.x < GB) ? 0 : 1;
    int gb = blockIdx.x - g * GB;
    const int* perm = g ? perm2 : perm1;
    unsigned char* keep = g ? g_keep2 : g_keep1;
    int* hop = g_hopG[g];
    int* invp = g_invpermG[g];
    int* hist = g_histG[g];
    unsigned* bar = &g_barG[g];
    unsigned epoch = 0;
    int gtid = gb * 1024 + threadIdx.x;
    int gsz = GB * 1024;
    const int INF = n;

    __shared__ int sWarp[32];
    __shared__ unsigned long long sK[32];

    int root = __ldg(&perm[0]);
    for (int i = gtid; i < n; i += gsz) {
        __stcg(&hop[i], (i == root) ? 0 : INF);
        __stcg(&invp[__ldg(&perm[i])], i);
        if (i != root) __stcg(&g_front[g][0][i - (i > root)], i);
    }
    {
        unsigned* B = &g_bmp[g][0][0];
        int rw = root >> 5;
        for (int i = gtid; i < 3 * BMPW; i += gsz)
            __stcg(&B[i], (i == rw) ? (1u << (root & 31)) : 0u);
    }
    for (int i = gtid; i < HIST_BINS; i += gsz) __stcg(&hist[i], 0);
    for (int i = gtid; i < MAX_SWEEPS + 8; i += gsz) __stcg(&g_szHist[g][i], 0);
    if (gtid == 0) {
        __stcg(&g_szHist[g][0], n - 1);
        g_seedkeyG[g] = ~0ull;
    }
    xsync(bar, GB, epoch);

    int vis = 1;
    int usz = n - 1;
    int t = 0;
    int lane = threadIdx.x & 31;
    while (vis <= k && t < MAX_SWEEPS) {
        const int* uin = g_front[g][t & 1];
        int* uout = g_front[g][(t + 1) & 1];
        int* ctr = &g_szHist[g][t + 1];
        const unsigned* bmpR = g_bmp[g][t % 3];
        unsigned* bmpW = g_bmp[g][(t + 1) % 3];
        unsigned* bmpC = g_bmp[g][(t + 2) % 3];
        for (int i = gtid; i < BMPW; i += gsz) __stcg(&bmpC[i], 0u);
        for (int idx = gtid; idx < usz; idx += gsz) {
            int v = __ldcg(&uin[idx]);
            if (__ldcg(&hop[v]) != INF) continue;
            int s0 = g_rowD[v], s1 = g_rowD[v + 1];
            bool found = false;
            int e2 = s0;
            for (; e2 + 4 <= s1; e2 += 4) {
                unsigned c0 = __ldg(&g_colD[e2]);
                unsigned c1 = __ldg(&g_colD[e2 + 1]);
                unsigned c2 = __ldg(&g_colD[e2 + 2]);
                unsigned c3 = __ldg(&g_colD[e2 + 3]);
                unsigned b = ((bmpR[c0 >> 5] >> (c0 & 31)) & 1u)
                           | ((bmpR[c1 >> 5] >> (c1 & 31)) & 1u)
                           | ((bmpR[c2 >> 5] >> (c2 & 31)) & 1u)
                           | ((bmpR[c3 >> 5] >> (c3 & 31)) & 1u);
                if (b) { found = true; break; }
            }
            if (!found) {
                for (; e2 < s1; e2++) {
                    unsigned c = __ldg(&g_colD[e2]);
                    if ((bmpR[c >> 5] >> (c & 31)) & 1u) { found = true; break; }
                }
            }
            if (found) {
                __stcg(&hop[v], t + 1);
                atomicOr(&bmpW[v >> 5], 1u << (v & 31));
            } else {
                cg::coalesced_group grp = cg::coalesced_threads();
                int base;
                if (grp.thread_rank() == 0) base = atomicAdd(ctr, (int)grp.size());
                base = grp.shfl(base, 0);
                __stcg(&uout[base + grp.thread_rank()], v);
            }
        }
        xsync(bar, GB, epoch);
        int newUsz = __ldcg(&g_szHist[g][t + 1]);
        t += 1;
        int visNow = n - newUsz;
        bool stuck = (visNow == vis);
        usz = newUsz;
        if (stuck) {
            unsigned long long key = ~0ull;
            {
                const int* ulist = g_front[g][t & 1];
                for (int idx = gtid; idx < newUsz; idx += gsz) {
                    int v = __ldcg(&ulist[idx]);
                    key = ullmin2(key, ((unsigned long long)(unsigned)__ldg(&perm[v]) << 32) | (unsigned)v);
                }
            }
#pragma unroll
            for (int off = 16; off; off >>= 1)
                key = ullmin2(key, __shfl_down_sync(0xffffffffu, key, off));
            int wid = threadIdx.x >> 5;
            if (lane == 0) sK[wid] = key;
            __syncthreads();
            if (threadIdx.x < 32) {
                unsigned long long kk2 = sK[threadIdx.x];
#pragma unroll
                for (int off = 16; off; off >>= 1)
                    kk2 = ullmin2(kk2, __shfl_down_sync(0xffffffffu, kk2, off));
                if (threadIdx.x == 0 && kk2 != ~0ull) atomicMin(&g_seedkeyG[g], kk2);
            }
            xsync(bar, GB, epoch);
            if (gtid == 0) {
                unsigned long long kv = g_seedkeyG[g];
                if (kv != ~0ull) {
                    int idx = (int)(unsigned)(kv & 0xffffffffull);
                    __stcg(&hop[idx], t);
                    atomicOr(&g_bmp[g][t % 3][idx >> 5], 1u << (idx & 31));
                }
                g_seedkeyG[g] = ~0ull;
            }
            xsync(bar, GB, epoch);
            vis = visNow + 1;
        } else {
            vis = visNow;
        }
    }

    {
        __shared__ int sh[256];
        for (int j = threadIdx.x; j < 256; j += 1024) sh[j] = 0;
        __syncthreads();
        for (int i = gtid; i < n; i += gsz) {
            int hv = min(__ldcg(&hop[i]), 15000);
            if (hv < 256) atomicAdd(&sh[hv], 1);
            else atomicAdd(&hist[hv], 1);
        }
        __syncthreads();
        for (int j = threadIdx.x; j < 256; j += 1024)
            if (sh[j]) atomicAdd(&hist[j], sh[j]);
    }
    xsync(bar, GB, epoch);

    if (gb == 0) {
        __shared__ int sRun, sTot, sDone;
        if (threadIdx.x == 0) { sRun = 0; sDone = 0; }
        __syncthreads();
        for (int base = 0; base < HIST_BINS; base += 1024) {
            if (sDone) break;
            int h = base + threadIdx.x;
            int v = (h < HIST_BINS) ? __ldcg(&hist[h]) : 0;
            int incl = blockScanInc(v, sWarp);
            int P = sRun + incl;
            if (v > 0 && P >= k && P - v < k) { g_hstarG[g] = h; g_rremG[g] = k - (P - v); sDone = 1; }
            if (threadIdx.x == 1023) sTot = incl;
            __syncthreads();
            if (threadIdx.x == 0) sRun += sTot;
            __syncthreads();
        }
    }
    xsync(bar, GB, epoch);
    int hstar = *(volatile int*)&g_hstarG[g];
    int rrem = *(volatile int*)&g_rremG[g];

    int chunk = (n + GB - 1) / GB;
    int v0 = gb * chunk, v1 = min(v0 + chunk, n);
    {
        int c = 0;
        for (int v = v0 + threadIdx.x; v < v1; v += 1024) {
            int j = __ldcg(&invp[v]);
            c += (min(__ldcg(&hop[j]), 15000) == hstar);
        }
#pragma unroll
        for (int off = 16; off; off >>= 1) c += __shfl_down_sync(0xffffffffu, c, off);
        int wid = threadIdx.x >> 5;
        if (lane == 0) sWarp[wid] = c;
        __syncthreads();
        if (threadIdx.x < 32) {
            int r = sWarp[threadIdx.x];
#pragma unroll
            for (int off = 16; off; off >>= 1) r += __shfl_down_sync(0xffffffffu, r, off);
            if (threadIdx.x == 0) g_blkCntG[g][gb] = r;
        }
    }
    xsync(bar, GB, epoch);
    if (gb == 0) {
        int b = threadIdx.x;
        int v = (b < GB) ? __ldcg(&g_blkCntG[g][b]) : 0;
        int incl = blockScanInc(v, sWarp);
        int excl = incl - v;
        if (b < GB && v > 0 && excl < rrem && rrem <= incl) {
            g_pselBlockG[g] = b; g_pselRemG[g] = rrem - excl;
        }
    }
    xsync(bar, GB, epoch);
    if (gb == *(volatile int*)&g_pselBlockG[g]) {
        int rem = *(volatile int*)&g_pselRemG[g];
        __shared__ int sRun2, sTot2, sDone2;
        if (threadIdx.x == 0) { sRun2 = 0; sDone2 = 0; }
        __syncthreads();
        for (int base = v0; base < v1; base += 1024) {
            if (sDone2) break;
            int v = base + threadIdx.x;
            int pred = 0;
            if (v < v1) {
                int j = __ldcg(&invp[v]);
                pred = (min(__ldcg(&hop[j]), 15000) == hstar);
            }
            int incl = blockScanInc(pred, sWarp);
            int cum = sRun2 + incl;
            if (pred && cum == rem) { g_pstarG[g] = v; sDone2 = 1; }
            if (threadIdx.x == 1023) sTot2 = incl;
            __syncthreads();
            if (threadIdx.x == 0) sRun2 += sTot2;
            __syncthreads();
        }
    }
    xsync(bar, GB, epoch);
    int pstar = *(volatile int*)&g_pstarG[g];
    for (int i = gtid; i < n; i += gsz) {
        int hv = min(__ldcg(&hop[i]), 15000);
        keep[i] = (hv < hstar) || (hv == hstar && __ldg(&perm[i]) <= pstar);
    }
    xexit(bar, GB, epoch);
}

// ============================================================================
// Kernel 3: annotate (warp per node): keep bits into colD + counts/inverses.
// ============================================================================

__global__ __launch_bounds__(256)
void annotate_kernel(int n) {
    int lane = threadIdx.x & 31;
    int warpId = (blockIdx.x * 256 + threadIdx.x) >> 5;
    int nW = gridDim.x * 8;
    for (int node = warpId; node < n; node += nW) {
        int s0 = g_rowD[node], s1 = g_rowD[node + 1];
        int c1 = 0, c2 = 0;
        for (int e = s0 + lane; e < s1; e += 32) {
            unsigned c = g_colD[e] & 0x3FFFFFFFu;
            unsigned k1 = (unsigned)__ldg(&g_keep1[c]);
            unsigned k2 = (unsigned)__ldg(&g_keep2[c]);
            g_colD[e] = c | (k1 << 30) | (k2 << 31);
            c1 += (int)k1; c2 += (int)k2;
        }
#pragma unroll
        for (int off = 16; off; off >>= 1) {
            c1 += __shfl_down_sync(0xffffffffu, c1, off);
            c2 += __shfl_down_sync(0xffffffffu, c2, off);
        }
        if (lane == 0) {
            g_inv1[node] = 1.f / (float)max(c1, 1);
            g_inv2[node] = 1.f / (float)max(c2, 1);
            g_invd[node] = 1.f / (float)max(s1 - s0, 1);
        }
    }
}

// ============================================================================
// Kernel 4: mega GCN — fp16 aggregation (single 8B PN gather per edge),
// f32x2 GEMV 2 nodes/warp, static smem; LAST block computes v.
// ============================================================================

#define MEGA_EDGE(cc)                                                          \
    do {                                                                       \
        unsigned s_ = (cc) & 0x3FFFFFFFu;                                      \
        ull pn_ = PN[(size_t)s_ * 32 + lane];                                  \
        __half2 f_ = u2h2((unsigned)pn_);                                      \
        __half2 g_ = u2h2((unsigned)(pn_ >> 32));                              \
        aP = __hadd2(aP, f_);                                                  \
        aN = __hadd2(aN, g_);                                                  \
        unsigned b1_ = (unsigned)(((int)((cc) << 1)) >> 31) & 0x3C003C00u;     \
        unsigned b2_ = (unsigned)(((int)(cc)) >> 31) & 0x3C003C00u;            \
        aM1 = __hfma2(f_, u2h2(b1_), aM1);                                     \
        aM2 = __hfma2(f_, u2h2(b2_), aM2);                                     \
    } while (0)

__global__ __launch_bounds__(256)
void mega_gcn_kernel(const float* __restrict__ Wenc, const float* __restrict__ Wdisc,
                     int n, int k) {
    __shared__ float sW[4096];
    __shared__ __align__(8) float sxp[8][64][2];
    __shared__ __align__(8) float sxn[8][64][2];
    __shared__ __align__(8) float sx1[8][64][2];
    __shared__ __align__(8) float sx2[8][64][2];
    __shared__ double sSum[128];
    __shared__ int sLast;
    int tid = threadIdx.x;
    for (int j = tid; j < 4096; j += 256) sW[j] = Wenc[j];
    if (tid < 128) sSum[tid] = 0.0;
    __syncthreads();
    int warp = tid >> 5, lane = tid & 31;
    double A10 = 0.0, A11 = 0.0, A20 = 0.0, A21 = 0.0;
    const ull* PN = g_featPN;

    for (int nb = (blockIdx.x * 8 + warp) * 2; nb < n; nb += gridDim.x * 16) {
        int k1d[2], k2d[2];
#pragma unroll
        for (int j = 0; j < 2; j++) {
            int node = nb + j;
            bool valid = node < n;
            k1d[j] = valid ? (int)g_keep1[node] : 0;
            k2d[j] = valid ? (int)g_keep2[node] : 0;
            int s0 = valid ? g_rowD[node] : 0;
            int s1 = valid ? g_rowD[node + 1] : 0;

            __half2 aP = u2h2(0), aN = u2h2(0), aM1 = u2h2(0), aM2 = u2h2(0);

            int e2 = s0;
            while (e2 < s1 && (e2 & 3)) { MEGA_EDGE(__ldcs(&g_colD[e2])); e2++; }
            for (; e2 + 4 <= s1; e2 += 4) {
                uint4 c4 = *reinterpret_cast<const uint4*>(&g_colD[e2]);
                MEGA_EDGE(c4.x); MEGA_EDGE(c4.y); MEGA_EDGE(c4.z); MEGA_EDGE(c4.w);
            }
            while (e2 < s1) { MEGA_EDGE(__ldcs(&g_colD[e2])); e2++; }

            float invd = valid ? __ldg(&g_invd[node]) : 1.f;
            float i1 = valid ? __ldg(&g_inv1[node]) : 1.f;
            float i2 = valid ? __ldg(&g_inv2[node]) : 1.f;
            float2 P = __half22float2(aP), Q = __half22float2(aN);
            float2 M1 = __half22float2(aM1), M2 = __half22float2(aM2);
            sxp[warp][2 * lane][j] = P.x * invd; sxp[warp][2 * lane + 1][j] = P.y * invd;
            sxn[warp][2 * lane][j] = Q.x * invd; sxn[warp][2 * lane + 1][j] = Q.y * invd;
            sx1[warp][2 * lane][j] = M1.x * i1;  sx1[warp][2 * lane + 1][j] = M1.y * i1;
            sx2[warp][2 * lane][j] = M2.x * i2;  sx2[warp][2 * lane + 1][j] = M2.y * i2;
        }
        __syncwarp();

        ull oPa = 0, oPb = 0, oNa = 0, oNb = 0;
        ull o1a = 0, o1b = 0, o2a = 0, o2b = 0;
#pragma unroll 16
        for (int kk = 0; kk < 64; kk++) {
            float2 w = *reinterpret_cast<const float2*>(&sW[kk * 64 + 2 * lane]);
            ull wa = pack2(w.x, w.x);
            ull wb = pack2(w.y, w.y);
            ull xp = *reinterpret_cast<const ull*>(&sxp[warp][kk][0]);
            ull xn = *reinterpret_cast<const ull*>(&sxn[warp][kk][0]);
            ull x1 = *reinterpret_cast<const ull*>(&sx1[warp][kk][0]);
            ull x2 = *reinterpret_cast<const ull*>(&sx2[warp][kk][0]);
            oPa = fma2(xp, wa, oPa); oPb = fma2(xp, wb, oPb);
            oNa = fma2(xn, wa, oNa); oNb = fma2(xn, wb, oNb);
            o1a = fma2(x1, wa, o1a); o1b = fma2(x1, wb, o1b);
            o2a = fma2(x2, wa, o2a); o2b = fma2(x2, wb, o2b);
        }
        float opa[2], opb[2], ona[2], onb[2], m1a[2], m1b[2], m2a[2], m2b[2];
        unpack2(oPa, opa[0], opa[1]); unpack2(oPb, opb[0], opb[1]);
        unpack2(oNa, ona[0], ona[1]); unpack2(oNb, onb[0], onb[1]);
        unpack2(o1a, m1a[0], m1a[1]); unpack2(o1b, m1b[0], m1b[1]);
        unpack2(o2a, m2a[0], m2a[1]); unpack2(o2b, m2b[0], m2b[1]);
#pragma unroll
        for (int j = 0; j < 2; j++) {
            int node = nb + j;
            if (node < n) {
                reinterpret_cast<__half2*>(g_hpos16)[(size_t)node * 32 + lane] =
                    __floats2half2_rn(fmaxf(opa[j], 0.f), fmaxf(opb[j], 0.f));
                reinterpret_cast<__half2*>(g_hneg16)[(size_t)node * 32 + lane] =
                    __floats2half2_rn(fmaxf(ona[j], 0.f), fmaxf(onb[j], 0.f));
                if (k1d[j]) { A10 += (double)fmaxf(m1a[j], 0.f); A11 += (double)fmaxf(m1b[j], 0.f); }
                if (k2d[j]) { A20 += (double)fmaxf(m2a[j], 0.f); A21 += (double)fmaxf(m2b[j], 0.f); }
            }
        }
        __syncwarp();
    }
    atomicAdd(&sSum[2 * lane], A10);
    atomicAdd(&sSum[2 * lane + 1], A11);
    atomicAdd(&sSum[64 + 2 * lane], A20);
    atomicAdd(&sSum[64 + 2 * lane + 1], A21);
    __syncthreads();
    if (tid < 128) {
        double v = sSum[tid];
        if (v != 0.0) atomicAdd(&g_summary[tid], v);
    }

    if (tid == 0) {
        __threadfence();
        sLast = (atomicAdd(&g_ctrMega, 1u) == gridDim.x - 1);
    }
    __syncthreads();
    if (sLast) {
        __shared__ float ss[2][64];
        if (tid < 128) {
            double s = g_summary[tid] / (double)k;
            ss[tid >> 6][tid & 63] = (float)(1.0 / (1.0 + exp(-s)));
        }
        __syncthreads();
        if (tid < 128) {
            int p = tid >> 6, c = tid & 63;
            float v = 0.f;
#pragma unroll
            for (int b = 0; b < 64; b++) v += Wdisc[c * 64 + b] * ss[p][b];
            g_v[p][c] = v;
        }
        if (tid == 0) g_ctrMega = 0;
    }
}

// ============================================================================
// Kernel 5: BCE losses — f32x2 packed 2-node reduction; last block finalizes.
// ============================================================================

__global__ __launch_bounds__(256)
void loss_kernel(float* __restrict__ out, int n) {
    __shared__ float sv0[64], sv1[64];
    __shared__ double sL[4];
    __shared__ int sLast;
    int tid = threadIdx.x;
    if (tid < 64) { sv0[tid] = g_v[0][tid]; sv1[tid] = g_v[1][tid]; }
    if (tid < 4) sL[tid] = 0.0;
    __syncthreads();
    int warp = tid >> 5, lane = tid & 31;
    float v00 = sv0[2 * lane], v01 = sv0[2 * lane + 1];
    float v10 = sv1[2 * lane], v11 = sv1[2 * lane + 1];
    double l0 = 0, l1 = 0, l2 = 0, l3 = 0;
    const __half2* HP = reinterpret_cast<const __half2*>(g_hpos16);
    const __half2* HN = reinterpret_cast<const __half2*>(g_hneg16);
    const ull ONE = pack2(1.f, 1.f);
    for (int nb = (blockIdx.x * 8 + warp) * 2; nb < n; nb += gridDim.x * 16) {
        float pA1 = 0, pA2 = 0, qA1 = 0, qA2 = 0;
        float pB1 = 0, pB2 = 0, qB1 = 0, qB2 = 0;
        {
            float2 hp = __half22float2(HP[(size_t)nb * 32 + lane]);
            float2 hn = __half22float2(HN[(size_t)nb * 32 + lane]);
            pA1 = hp.x * v00 + hp.y * v01;
            pA2 = hp.x * v10 + hp.y * v11;
            qA1 = hn.x * v00 + hn.y * v01;
            qA2 = hn.x * v10 + hn.y * v11;
        }
        if (nb + 1 < n) {
            float2 hp = __half22float2(HP[(size_t)(nb + 1) * 32 + lane]);
            float2 hn = __half22float2(HN[(size_t)(nb + 1) * 32 + lane]);
            pB1 = hp.x * v00 + hp.y * v01;
            pB2 = hp.x * v10 + hp.y * v11;
            qB1 = hn.x * v00 + hn.y * v01;
            qB2 = hn.x * v10 + hn.y * v11;
        }
        // pack (nodeA, nodeB) per logit; one shuffle tree reduces both
        ull P1 = pack2(pA1, pB1), P2 = pack2(pA2, pB2);
        ull Q1 = pack2(qA1, qB1), Q2 = pack2(qA2, qB2);
#pragma unroll
        for (int off = 16; off; off >>= 1) {
            P1 = fma2(__shfl_down_sync(0xffffffffu, P1, off), ONE, P1);
            P2 = fma2(__shfl_down_sync(0xffffffffu, P2, off), ONE, P2);
            Q1 = fma2(__shfl_down_sync(0xffffffffu, Q1, off), ONE, Q1);
            Q2 = fma2(__shfl_down_sync(0xffffffffu, Q2, off), ONE, Q2);
        }
        if (lane == 0) {
            float a, b;
            unpack2(P1, a, b);
            l0 += (double)softplusf(-a);
            if (nb + 1 < n) l0 += (double)softplusf(-b);
            unpack2(Q1, a, b);
            l1 += (double)softplusf(a);
            if (nb + 1 < n) l1 += (double)softplusf(b);
            unpack2(P2, a, b);
            l2 += (double)softplusf(-a);
            if (nb + 1 < n) l2 += (double)softplusf(-b);
            unpack2(Q2, a, b);
            l3 += (double)softplusf(a);
            if (nb + 1 < n) l3 += (double)softplusf(b);
        }
    }
    if (lane == 0) {
        atomicAdd(&sL[0], l0); atomicAdd(&sL[1], l1);
        atomicAdd(&sL[2], l2); atomicAdd(&sL[3], l3);
    }
    __syncthreads();
    if (tid < 4) atomicAdd(&g_loss[tid], sL[tid]);

    if (tid == 0) {
        __threadfence();
        sLast = (atomicAdd(&g_ctrLoss, 1u) == gridDim.x - 1);
    }
    __syncthreads();
    if (sLast && tid == 0) {
        out[0] = (float)((g_loss[0] + g_loss[1] + g_loss[2] + g_loss[3]) / (double)n);
        g_ctrLoss = 0;
    }
}

// ============================================================================
// launch
// ============================================================================

extern "C" void kernel_launch(void* const* d_in, const int* in_sizes, int n_in,
                              void* d_out, int out_size) {
    const float* feat = (const float*)d_in[0];
    const float* Wenc = (const float*)d_in[1];
    const float* Wdisc = (const float*)d_in[2];
    const int* src = (const int*)d_in[3];
    const int* dst = (const int*)d_in[4];
    const int* permneg = (const int*)d_in[5];
    const int* perm1 = (const int*)d_in[6];
    const int* perm2 = (const int*)d_in[7];

    int e = in_sizes[3];
    int n = in_sizes[5];
    int k = (int)((double)n * 0.8);

    csr_kernel<<<CSRB, 1024>>>(feat, src, dst, permneg, e, n);
    bfs_dual_kernel<<<BFSB, 1024>>>(perm1, perm2, n, k);

    int aGrid = (n + 7) / 8;
    if (aGrid > 1480) aGrid = 1480;
    annotate_kernel<<<aGrid, 256>>>(n);

    int mGrid = (n + 15) / 16;
    if (mGrid > 1480) mGrid = 1480;
    mega_gcn_kernel<<<mGrid, 256>>>(Wenc, Wdisc, n, k);

    int lGrid = (n + 15) / 16;
    if (lGrid > 1480) lGrid = 1480;
    loss_kernel<<<lGrid, 256>>>((float*)d_out, n);
}